// round 1
// baseline (speedup 1.0000x reference)
#include <cuda_runtime.h>
#include <math.h>

#define D_MODEL   1024
#define D_STATE   64
#define D_CONV    4
#define D_INNER   2048
#define NHEADS    32
#define HEADDIM   64
#define CHUNK     64
#define CONV_DIM  2176            // D_INNER + 2*D_STATE
#define D_IN_PROJ 4256            // 2*D_INNER + 2*D_STATE + NHEADS
#define B_SZ      2
#define T_LEN     4096
#define M_TOK     (B_SZ * T_LEN)  // 8192
#define NCHUNK    (T_LEN / CHUNK) // 64

// ---------------- scratch (device globals; no allocations allowed) ----------
__device__ float g_zxbcdt[(size_t)M_TOK * D_IN_PROJ];   // 139.5 MB
__device__ float g_xbc[(size_t)M_TOK * CONV_DIM];       // 71.3 MB (post conv+silu)
__device__ float g_dt[(size_t)M_TOK * NHEADS];          // softplus'ed dt
__device__ float g_y[(size_t)M_TOK * D_INNER];          // ssd output, then normed in place

// ---------------- generic fp32 NT GEMM: C[M,N] = A[M,K] @ B[N,K]^T -----------
// BM=BN=64, BK=16, 256 threads, 4x4 per thread, float4 global loads.
__global__ void gemm_nt_kernel(const float* __restrict__ A,
                               const float* __restrict__ B,
                               float* __restrict__ C,
                               int M, int N, int K) {
    __shared__ float sA[16][64];
    __shared__ float sB[16][64];

    const int tid = threadIdx.x;
    const int tx = tid & 15;        // 0..15 -> n tile
    const int ty = tid >> 4;        // 0..15 -> m tile
    const int m0 = blockIdx.y << 6;
    const int n0 = blockIdx.x << 6;

    const int li = tid >> 2;          // 0..63 row within tile
    const int lk = (tid & 3) << 2;    // 0,4,8,12 k offset

    const float* Aptr = A + (size_t)(m0 + li) * K + lk;
    const bool   bval = (n0 + li) < N;
    const float* Bptr = B + (size_t)(n0 + li) * K + lk;

    float acc[4][4];
#pragma unroll
    for (int i = 0; i < 4; i++)
#pragma unroll
        for (int j = 0; j < 4; j++) acc[i][j] = 0.f;

    for (int k0 = 0; k0 < K; k0 += 16) {
        float4 va = *reinterpret_cast<const float4*>(Aptr + k0);
        float4 vb = bval ? *reinterpret_cast<const float4*>(Bptr + k0)
                         : make_float4(0.f, 0.f, 0.f, 0.f);
        sA[lk + 0][li] = va.x; sA[lk + 1][li] = va.y;
        sA[lk + 2][li] = va.z; sA[lk + 3][li] = va.w;
        sB[lk + 0][li] = vb.x; sB[lk + 1][li] = vb.y;
        sB[lk + 2][li] = vb.z; sB[lk + 3][li] = vb.w;
        __syncthreads();

#pragma unroll
        for (int kk = 0; kk < 16; kk++) {
            float ra[4], rb[4];
#pragma unroll
            for (int i = 0; i < 4; i++) ra[i] = sA[kk][(ty << 2) + i];
#pragma unroll
            for (int j = 0; j < 4; j++) rb[j] = sB[kk][(tx << 2) + j];
#pragma unroll
            for (int i = 0; i < 4; i++)
#pragma unroll
                for (int j = 0; j < 4; j++) acc[i][j] += ra[i] * rb[j];
        }
        __syncthreads();
    }

#pragma unroll
    for (int i = 0; i < 4; i++) {
        const int m = m0 + (ty << 2) + i;
#pragma unroll
        for (int j = 0; j < 4; j++) {
            const int n = n0 + (tx << 2) + j;
            if (n < N) C[(size_t)m * N + n] = acc[i][j];
        }
    }
}

// ---------------- dt = softplus(raw_dt + dt_bias) ---------------------------
__global__ void dt_kernel(const float* __restrict__ dt_bias) {
    const int idx = blockIdx.x * 256 + threadIdx.x;   // [M_TOK*NHEADS)
    const int m = idx >> 5;
    const int h = idx & 31;
    float v = g_zxbcdt[(size_t)m * D_IN_PROJ + (D_INNER + CONV_DIM) + h] + dt_bias[h];
    g_dt[idx] = (v > 20.f) ? v : log1pf(expf(v));
}

// ---------------- causal depthwise conv (w=4) + bias + SiLU -----------------
__global__ void conv_silu_kernel(const float* __restrict__ w,
                                 const float* __restrict__ bias) {
    const int c = blockIdx.x * 128 + threadIdx.x;     // channel in [0, CONV_DIM)
    const int m = blockIdx.y;                         // flat token
    const int t = m & (T_LEN - 1);                    // time within batch
    float acc = bias[c];
#pragma unroll
    for (int j = 0; j < 4; j++) {
        const int tt = t - 3 + j;
        if (tt >= 0)
            acc += w[c * 4 + j] *
                   g_zxbcdt[(size_t)(m - 3 + j) * D_IN_PROJ + D_INNER + c];
    }
    g_xbc[(size_t)m * CONV_DIM + c] = acc / (1.f + expf(-acc));
}

// ---------------- SSD: one block per (batch, head), sequential over chunks --
// dyn smem: state(64x65) x(64x65) B(64x65) C(64x65) G(64x65) + cum/dt/coef(64 ea)
#define SPITCH 65
#define STILE  (64 * SPITCH)
__global__ void ssd_kernel(const float* __restrict__ A_log,
                           const float* __restrict__ Dvec) {
    extern __shared__ float sm[];
    float* s_state = sm;
    float* s_x     = sm + STILE;
    float* s_B     = sm + 2 * STILE;
    float* s_C     = sm + 3 * STILE;
    float* s_G     = sm + 4 * STILE;
    float* s_cum   = sm + 5 * STILE;
    float* s_dt    = s_cum + 64;
    float* s_coef  = s_dt + 64;

    const int b = blockIdx.x >> 5;
    const int h = blockIdx.x & 31;
    const float Ah = -expf(A_log[h]);
    const float Dh = Dvec[h];

    const int tid = threadIdx.x;       // 256
    const int r  = tid >> 2;           // 0..63
    const int c0 = (tid & 3) << 4;     // 0,16,32,48

#pragma unroll
    for (int j = 0; j < 16; j++) s_state[r * SPITCH + c0 + j] = 0.f;
    __syncthreads();

    for (int c = 0; c < NCHUNK; c++) {
        const int m0 = b * T_LEN + c * CHUNK;

        // cooperative load of x / B / C tiles (64x64 each)
#pragma unroll
        for (int i = 0; i < 16; i++) {
            const int idx = tid + i * 256;
            const int l = idx >> 6, q = idx & 63;
            const size_t row = (size_t)(m0 + l) * CONV_DIM;
            s_x[l * SPITCH + q] = g_xbc[row + h * HEADDIM + q];
            s_B[l * SPITCH + q] = g_xbc[row + D_INNER + q];
            s_C[l * SPITCH + q] = g_xbc[row + D_INNER + D_STATE + q];
        }
        if (tid < 64) s_dt[tid] = g_dt[(size_t)(m0 + tid) * NHEADS + h];
        __syncthreads();

        if (tid == 0) {
            float cum = 0.f;
            for (int l = 0; l < 64; l++) { cum += Ah * s_dt[l]; s_cum[l] = cum; }
        }
        __syncthreads();
        if (tid < 64) s_coef[tid] = s_dt[tid] * expf(s_cum[63] - s_cum[tid]);

        // ---- step A: scores G(l,s) = sum_n C(l,n)B(s,n);  M = G*L*dt[s] ----
        float acc[16];
#pragma unroll
        for (int j = 0; j < 16; j++) acc[j] = 0.f;
        for (int n = 0; n < 64; n++) {
            const float cv = s_C[r * SPITCH + n];
#pragma unroll
            for (int j = 0; j < 16; j++) acc[j] += cv * s_B[(c0 + j) * SPITCH + n];
        }
        const float cumr = s_cum[r];
#pragma unroll
        for (int j = 0; j < 16; j++) {
            const int s = c0 + j;
            const float v = (s <= r) ? acc[j] * expf(cumr - s_cum[s]) * s_dt[s] : 0.f;
            s_G[r * SPITCH + s] = v;
        }
        __syncthreads();

        // ---- step B: Y_diag(l,p) = sum_s M(l,s) x(s,p) ----
        float yv[16];
#pragma unroll
        for (int j = 0; j < 16; j++) yv[j] = 0.f;
        for (int s = 0; s < 64; s++) {
            const float mval = s_G[r * SPITCH + s];
#pragma unroll
            for (int j = 0; j < 16; j++) yv[j] += mval * s_x[s * SPITCH + c0 + j];
        }
        // ---- step C: Y_off(l,p) = exp(cum_l) * sum_n C(l,n) state(p,n) ----
        float off[16];
#pragma unroll
        for (int j = 0; j < 16; j++) off[j] = 0.f;
        for (int n = 0; n < 64; n++) {
            const float cv = s_C[r * SPITCH + n];
#pragma unroll
            for (int j = 0; j < 16; j++) off[j] += cv * s_state[(c0 + j) * SPITCH + n];
        }
        const float el = expf(cumr);
        const size_t orow = (size_t)(m0 + r) * D_INNER + h * HEADDIM;
#pragma unroll
        for (int j = 0; j < 16; j++)
            g_y[orow + c0 + j] = yv[j] + el * off[j] + s_x[r * SPITCH + c0 + j] * Dh;
        __syncthreads();   // all state reads complete before update

        // ---- step D: state(p,n) = exp(cum63)*state + sum_l coef(l) x(l,p) B(l,n)
        const float eT = expf(s_cum[63]);
        float st[16];
#pragma unroll
        for (int j = 0; j < 16; j++) st[j] = s_state[r * SPITCH + c0 + j] * eT;
        for (int l = 0; l < 64; l++) {
            const float xv = s_coef[l] * s_x[l * SPITCH + r];
#pragma unroll
            for (int j = 0; j < 16; j++) st[j] += xv * s_B[l * SPITCH + c0 + j];
        }
#pragma unroll
        for (int j = 0; j < 16; j++) s_state[r * SPITCH + c0 + j] = st[j];
        __syncthreads();   // before next chunk overwrites x/B/C
    }
}

// ---------------- gate (y * silu(z)) + RMSNorm, in place on g_y -------------
__global__ void gate_rms_kernel(const float* __restrict__ norm_w) {
    const int m = blockIdx.x;
    const int tid = threadIdx.x;
    const size_t ybase = (size_t)m * D_INNER;
    const size_t zbase = (size_t)m * D_IN_PROJ;
    float vals[8];
    float ssum = 0.f;
#pragma unroll
    for (int i = 0; i < 8; i++) {
        const int idx = tid + i * 256;
        const float yv = g_y[ybase + idx];
        const float z  = g_zxbcdt[zbase + idx];
        const float g  = yv * z / (1.f + expf(-z));
        vals[i] = g;
        ssum += g * g;
    }
    __shared__ float red[256];
    red[tid] = ssum;
    __syncthreads();
    for (int s = 128; s > 0; s >>= 1) {
        if (tid < s) red[tid] += red[tid + s];
        __syncthreads();
    }
    const float scale = rsqrtf(red[0] / (float)D_INNER + 1e-5f);
#pragma unroll
    for (int i = 0; i < 8; i++) {
        const int idx = tid + i * 256;
        g_y[ybase + idx] = vals[i] * scale * norm_w[idx];
    }
}

// ---------------------------------------------------------------------------
extern "C" void kernel_launch(void* const* d_in, const int* in_sizes, int n_in,
                              void* d_out, int out_size) {
    const float* u       = (const float*)d_in[0];
    const float* W_in    = (const float*)d_in[1];
    const float* conv_w  = (const float*)d_in[2];
    const float* conv_b  = (const float*)d_in[3];
    const float* dt_bias = (const float*)d_in[4];
    const float* A_log   = (const float*)d_in[5];
    const float* Dv      = (const float*)d_in[6];
    const float* norm_w  = (const float*)d_in[7];
    const float* W_out   = (const float*)d_in[8];
    float* out = (float*)d_out;

    float *zx_p, *y_p;
    cudaGetSymbolAddress((void**)&zx_p, g_zxbcdt);
    cudaGetSymbolAddress((void**)&y_p, g_y);

    // 1) zxbcdt = u @ W_in^T   (8192 x 4256 x 1024)
    gemm_nt_kernel<<<dim3((D_IN_PROJ + 63) / 64, M_TOK / 64), 256>>>(
        u, W_in, zx_p, M_TOK, D_IN_PROJ, D_MODEL);

    // 2) dt = softplus(dt + bias)
    dt_kernel<<<(M_TOK * NHEADS) / 256, 256>>>(dt_bias);

    // 3) depthwise causal conv + SiLU
    conv_silu_kernel<<<dim3(CONV_DIM / 128, M_TOK), 128>>>(conv_w, conv_b);

    // 4) SSD chunked scan
    const int ssd_smem = (5 * STILE + 3 * 64) * (int)sizeof(float);  // ~84 KB
    cudaFuncSetAttribute(ssd_kernel, cudaFuncAttributeMaxDynamicSharedMemorySize,
                         ssd_smem);
    ssd_kernel<<<B_SZ * NHEADS, 256, ssd_smem>>>(A_log, Dv);

    // 5) gate + RMSNorm (in place on g_y)
    gate_rms_kernel<<<M_TOK, 256>>>(norm_w);

    // 6) out = y_n @ W_out^T   (8192 x 1024 x 2048)
    gemm_nt_kernel<<<dim3(D_MODEL / 64, M_TOK / 64), 256>>>(
        y_p, W_out, out, M_TOK, D_MODEL, D_INNER);
}

// round 3
// speedup vs baseline: 4.0589x; 4.0589x over previous
#include <cuda_runtime.h>
#include <cuda_bf16.h>
#include <math.h>
#include <stdint.h>

#define D_MODEL   1024
#define D_STATE   64
#define D_CONV    4
#define D_INNER   2048
#define NHEADS    32
#define HEADDIM   64
#define CHUNK     64
#define CONV_DIM  2176
#define D_IN_PROJ 4256
#define B_SZ      2
#define T_LEN     4096
#define M_TOK     (B_SZ * T_LEN)   // 8192
#define NCHUNK    (T_LEN / CHUNK)  // 64
#define NBH       (B_SZ * NHEADS)  // 64

// ------------------------- scratch (device globals) -------------------------
__device__ float g_zxbcdt[(size_t)M_TOK * D_IN_PROJ];
__device__ float g_xbc[(size_t)M_TOK * CONV_DIM];
__device__ float g_dt[(size_t)M_TOK * NHEADS];
__device__ float g_y[(size_t)M_TOK * D_INNER];

__device__ __nv_bfloat16 g_uh[(size_t)M_TOK * D_MODEL];
__device__ __nv_bfloat16 g_ul[(size_t)M_TOK * D_MODEL];
__device__ __nv_bfloat16 g_wih[(size_t)D_IN_PROJ * D_MODEL];
__device__ __nv_bfloat16 g_wil[(size_t)D_IN_PROJ * D_MODEL];
__device__ __nv_bfloat16 g_yh[(size_t)M_TOK * D_INNER];
__device__ __nv_bfloat16 g_yl[(size_t)M_TOK * D_INNER];
__device__ __nv_bfloat16 g_woh[(size_t)D_MODEL * D_INNER];
__device__ __nv_bfloat16 g_wol[(size_t)D_MODEL * D_INNER];

__device__ float g_cs[(size_t)NBH * NCHUNK * 64 * 64];
__device__ float g_ps[(size_t)NBH * NCHUNK * 64 * 64];
__device__ float g_T[NBH * NCHUNK];
__device__ float g_el[(size_t)NBH * NCHUNK * CHUNK];

// ------------------------- helpers ------------------------------------------
__device__ __forceinline__ uint32_t smem_u32(const void* p) {
    uint32_t a;
    asm("{ .reg .u64 t; cvta.to.shared.u64 t, %1; cvt.u32.u64 %0, t; }"
        : "=r"(a) : "l"(p));
    return a;
}
__device__ __forceinline__ void ldsm_x4(uint32_t& r0, uint32_t& r1,
                                        uint32_t& r2, uint32_t& r3,
                                        uint32_t addr) {
    asm volatile("ldmatrix.sync.aligned.m8n8.x4.shared.b16 {%0,%1,%2,%3}, [%4];"
                 : "=r"(r0), "=r"(r1), "=r"(r2), "=r"(r3) : "r"(addr));
}
__device__ __forceinline__ void mma_bf16(float* c, const uint32_t* a,
                                         uint32_t b0, uint32_t b1) {
    asm volatile(
        "mma.sync.aligned.m16n8k16.row.col.f32.bf16.bf16.f32 "
        "{%0,%1,%2,%3}, {%4,%5,%6,%7}, {%8,%9}, {%0,%1,%2,%3};"
        : "+f"(c[0]), "+f"(c[1]), "+f"(c[2]), "+f"(c[3])
        : "r"(a[0]), "r"(a[1]), "r"(a[2]), "r"(a[3]), "r"(b0), "r"(b1));
}
__device__ __forceinline__ void cp16(uint32_t dst, const void* src) {
    asm volatile("cp.async.cg.shared.global [%0], [%1], 16;"
                 :: "r"(dst), "l"(src));
}
__device__ __forceinline__ void cp16z(uint32_t dst, const void* src, int valid) {
    int sz = valid ? 16 : 0;
    asm volatile("cp.async.cg.shared.global [%0], [%1], 16, %2;"
                 :: "r"(dst), "l"(src), "r"(sz));
}
#define CP_COMMIT() asm volatile("cp.async.commit_group;" ::: "memory")
#define CP_WAIT(N)  asm volatile("cp.async.wait_group %0;" :: "n"(N) : "memory")

// smem tile layout: [128 rows][32 bf16] = 64 B/row, 16B chunks XOR-swizzled.
__device__ __forceinline__ uint32_t swz(int row, int kb) {
    return (uint32_t)(row * 64 + ((((kb >> 4) ^ (row & 3)) << 4) | (kb & 15)));
}

// ------------------------- split fp32 -> bf16 hi/lo -------------------------
__global__ void split_kernel(const float* __restrict__ src,
                             __nv_bfloat16* __restrict__ hi,
                             __nv_bfloat16* __restrict__ lo, int n) {
    int i = blockIdx.x * 256 + threadIdx.x;
    if (i < n) {
        float v = src[i];
        __nv_bfloat16 h = __float2bfloat16(v);
        hi[i] = h;
        lo[i] = __float2bfloat16(v - __bfloat162float(h));
    }
}

// ------------------------- HMMA GEMM: C[M,N] = A[M,K] @ B[N,K]^T ------------
// bf16 hi/lo split (3 products). BM=128, BN=128, BK=32, 8 warps (2m x 4n),
// warp tile 64x32. cp.async double-buffered smem, XOR-swizzle + ldmatrix.
#define TILE_B   8192                     // one 128x32 bf16 tile
#define STAGE_B  (4 * TILE_B)             // Ah Al Bh Bl
#define GEMM_SMEM (2 * STAGE_B)           // 64 KB
__global__ void __launch_bounds__(256) gemm_mma_kernel(
    const __nv_bfloat16* __restrict__ Ah, const __nv_bfloat16* __restrict__ Al,
    const __nv_bfloat16* __restrict__ Bh, const __nv_bfloat16* __restrict__ Bl,
    float* __restrict__ C, int M, int N, int K) {
    extern __shared__ char smem[];
    const uint32_t sb = smem_u32(smem);

    const int tid  = threadIdx.x;
    const int wid  = tid >> 5;
    const int lane = tid & 31;
    const int m0 = blockIdx.y << 7;
    const int n0 = blockIdx.x << 7;
    const int wm0 = (wid >> 2) << 6;       // 0 or 64
    const int wn0 = (wid & 3) << 5;        // 0,32,64,96

    // loader mapping: per array, 512 16B-chunks; thread t -> chunks t, t+256
    const int r0c = tid >> 2, c0c = tid & 3;            // chunk t
    const int r1c = (tid + 256) >> 2, c1c = tid & 3;    // chunk t+256

    float acc[4][4][4];
#pragma unroll
    for (int f = 0; f < 4; f++)
#pragma unroll
        for (int g = 0; g < 4; g++)
#pragma unroll
            for (int e = 0; e < 4; e++) acc[f][g][e] = 0.f;

    const int nk = K >> 5;

    // ---- stage loader ----
    auto load_stage = [&](int kc, int s) {
        const int k0 = kc << 5;
        const uint32_t st = sb + s * STAGE_B;
        // A hi/lo (always in bounds: M multiple of 128)
        {
            const size_t o0 = (size_t)(m0 + r0c) * K + k0 + c0c * 8;
            const size_t o1 = (size_t)(m0 + r1c) * K + k0 + c1c * 8;
            uint32_t d0 = st + swz(r0c, c0c * 16);
            uint32_t d1 = st + swz(r1c, c1c * 16);
            cp16(d0, Ah + o0);  cp16(d1, Ah + o1);
            cp16(d0 + TILE_B, Al + o0);  cp16(d1 + TILE_B, Al + o1);
        }
        // B hi/lo (guard rows)
        {
            const int v0 = (n0 + r0c) < N, v1 = (n0 + r1c) < N;
            const size_t o0 = v0 ? (size_t)(n0 + r0c) * K + k0 + c0c * 8 : 0;
            const size_t o1 = v1 ? (size_t)(n0 + r1c) * K + k0 + c1c * 8 : 0;
            uint32_t d0 = st + 2 * TILE_B + swz(r0c, c0c * 16);
            uint32_t d1 = st + 2 * TILE_B + swz(r1c, c1c * 16);
            cp16z(d0, Bh + o0, v0);  cp16z(d1, Bh + o1, v1);
            cp16z(d0 + TILE_B, Bl + o0, v0);  cp16z(d1 + TILE_B, Bl + o1, v1);
        }
        CP_COMMIT();
    };

    load_stage(0, 0);

    // per-lane ldmatrix address components
    const int a_row = lane & 15;           // row within 16-row frag
    const int a_kb  = (lane >> 4) << 4;    // 0/16 byte k-half
    const int b_row = (lane & 7) + ((lane >> 4) << 3);  // row within 16-row pair
    const int b_kb  = ((lane >> 3) & 1) << 4;

    for (int kc = 0; kc < nk; kc++) {
        if (kc + 1 < nk) load_stage(kc + 1, (kc + 1) & 1);
        if (kc + 1 < nk) { CP_WAIT(1); } else { CP_WAIT(0); }
        __syncthreads();

        const uint32_t st  = sb + (kc & 1) * STAGE_B;
        const uint32_t sAh = st, sAl = st + TILE_B;
        const uint32_t sBh = st + 2 * TILE_B, sBl = st + 3 * TILE_B;

#pragma unroll
        for (int kk = 0; kk < 2; kk++) {
            const int kb_a = kk * 32 + a_kb;
            const int kb_b = kk * 32 + b_kb;
            uint32_t ah[4][4], al[4][4], bh[2][4], bl[2][4];
#pragma unroll
            for (int f = 0; f < 4; f++) {
                const int row = wm0 + f * 16 + a_row;
                ldsm_x4(ah[f][0], ah[f][1], ah[f][2], ah[f][3],
                        sAh + swz(row, kb_a));
                ldsm_x4(al[f][0], al[f][1], al[f][2], al[f][3],
                        sAl + swz(row, kb_a));
            }
#pragma unroll
            for (int g2 = 0; g2 < 2; g2++) {
                const int row = wn0 + g2 * 16 + b_row;
                ldsm_x4(bh[g2][0], bh[g2][1], bh[g2][2], bh[g2][3],
                        sBh + swz(row, kb_b));
                ldsm_x4(bl[g2][0], bl[g2][1], bl[g2][2], bl[g2][3],
                        sBl + swz(row, kb_b));
            }
#pragma unroll
            for (int f = 0; f < 4; f++)
#pragma unroll
                for (int g = 0; g < 4; g++) {
                    const uint32_t* bhf = &bh[g >> 1][(g & 1) << 1];
                    const uint32_t* blf = &bl[g >> 1][(g & 1) << 1];
                    mma_bf16(acc[f][g], ah[f], bhf[0], bhf[1]);
                    mma_bf16(acc[f][g], ah[f], blf[0], blf[1]);
                    mma_bf16(acc[f][g], al[f], bhf[0], bhf[1]);
                }
        }
        __syncthreads();
    }

    // ---- epilogue: direct float2 stores ----
    const int er = lane >> 2;
    const int ec = (lane & 3) << 1;
#pragma unroll
    for (int f = 0; f < 4; f++) {
        const int row = m0 + wm0 + f * 16 + er;
#pragma unroll
        for (int g = 0; g < 4; g++) {
            const int col = n0 + wn0 + g * 8 + ec;
            if (col < N) {
                *(float2*)&C[(size_t)row * N + col] =
                    make_float2(acc[f][g][0], acc[f][g][1]);
                *(float2*)&C[(size_t)(row + 8) * N + col] =
                    make_float2(acc[f][g][2], acc[f][g][3]);
            }
        }
    }
}

// ------------------------- dt = softplus(raw + bias) ------------------------
__global__ void dt_kernel(const float* __restrict__ dt_bias) {
    const int idx = blockIdx.x * 256 + threadIdx.x;
    const int m = idx >> 5;
    const int h = idx & 31;
    float v = g_zxbcdt[(size_t)m * D_IN_PROJ + (D_INNER + CONV_DIM) + h] + dt_bias[h];
    g_dt[idx] = (v > 20.f) ? v : log1pf(expf(v));
}

// ------------------------- depthwise causal conv + SiLU ---------------------
__global__ void conv_silu_kernel(const float* __restrict__ w,
                                 const float* __restrict__ bias) {
    const int c = blockIdx.x * 128 + threadIdx.x;
    const int m = blockIdx.y;
    const int t = m & (T_LEN - 1);
    float acc = bias[c];
#pragma unroll
    for (int j = 0; j < 4; j++) {
        const int tt = t - 3 + j;
        if (tt >= 0)
            acc += w[c * 4 + j] *
                   g_zxbcdt[(size_t)(m - 3 + j) * D_IN_PROJ + D_INNER + c];
    }
    g_xbc[(size_t)m * CONV_DIM + c] = acc / (1.f + expf(-acc));
}

// ------------------------- SSD phase 1: intra-chunk -------------------------
#define SP 65
__global__ void __launch_bounds__(256) ssd_phase1(const float* __restrict__ A_log,
                                                  const float* __restrict__ Dvec) {
    extern __shared__ float sm[];
    float* s_x = sm;
    float* s_B = s_x + 64 * SP;
    float* s_C = s_B + 64 * SP;
    float* s_G = s_C + 64 * SP;
    float* s_cum = s_G + 64 * SP;
    float* s_dt = s_cum + 64;
    float* s_coef = s_dt + 64;

    const int blk = blockIdx.x;
    const int c = blk & (NCHUNK - 1);
    const int bh = blk >> 6;
    const int b = bh >> 5, h = bh & 31;
    const int tid = threadIdx.x;
    const int tr = (tid >> 4) << 2;
    const int tc = (tid & 15) << 2;
    const float Ah = -expf(A_log[h]);
    const float Dh = Dvec[h];
    const int m0 = b * T_LEN + c * CHUNK;

#pragma unroll
    for (int i = 0; i < 16; i++) {
        int idx = tid + (i << 8);
        int l = idx >> 6, q = idx & 63;
        size_t row = (size_t)(m0 + l) * CONV_DIM;
        s_x[l * SP + q] = g_xbc[row + h * HEADDIM + q];
        s_B[l * SP + q] = g_xbc[row + D_INNER + q];
        s_C[l * SP + q] = g_xbc[row + D_INNER + D_STATE + q];
    }
    if (tid < 64) s_dt[tid] = g_dt[(size_t)(m0 + tid) * NHEADS + h];
    __syncthreads();
    if (tid == 0) {
        float cum = 0.f;
        for (int l = 0; l < 64; l++) { cum += Ah * s_dt[l]; s_cum[l] = cum; }
    }
    __syncthreads();
    if (tid < 64) {
        s_coef[tid] = s_dt[tid] * __expf(s_cum[63] - s_cum[tid]);
        g_el[(size_t)blk * 64 + tid] = __expf(s_cum[tid]);
    }
    if (tid == 0) g_T[blk] = __expf(s_cum[63]);
    __syncthreads();

    float a[4][4] = {};
    for (int n = 0; n < 64; n++) {
        float cv[4], bv[4];
#pragma unroll
        for (int i = 0; i < 4; i++) cv[i] = s_C[(tr + i) * SP + n];
#pragma unroll
        for (int j = 0; j < 4; j++) bv[j] = s_B[(tc + j) * SP + n];
#pragma unroll
        for (int i = 0; i < 4; i++)
#pragma unroll
            for (int j = 0; j < 4; j++) a[i][j] += cv[i] * bv[j];
    }
#pragma unroll
    for (int i = 0; i < 4; i++) {
        const int l = tr + i;
        const float cl = s_cum[l];
#pragma unroll
        for (int j = 0; j < 4; j++) {
            const int s = tc + j;
            s_G[l * SP + s] =
                (s <= l) ? a[i][j] * __expf(cl - s_cum[s]) * s_dt[s] : 0.f;
        }
    }
    __syncthreads();

    float y[4][4] = {};
    for (int s = 0; s < 64; s++) {
        float gv[4], xv[4];
#pragma unroll
        for (int i = 0; i < 4; i++) gv[i] = s_G[(tr + i) * SP + s];
#pragma unroll
        for (int j = 0; j < 4; j++) xv[j] = s_x[s * SP + tc + j];
#pragma unroll
        for (int i = 0; i < 4; i++)
#pragma unroll
            for (int j = 0; j < 4; j++) y[i][j] += gv[i] * xv[j];
    }
#pragma unroll
    for (int i = 0; i < 4; i++) {
        const size_t orow = (size_t)(m0 + tr + i) * D_INNER + h * HEADDIM;
#pragma unroll
        for (int j = 0; j < 4; j++)
            g_y[orow + tc + j] = y[i][j] + Dh * s_x[(tr + i) * SP + tc + j];
    }

    float stt[4][4] = {};
    for (int l = 0; l < 64; l++) {
        const float cf = s_coef[l];
        float xv[4], bv[4];
#pragma unroll
        for (int i = 0; i < 4; i++) xv[i] = cf * s_x[l * SP + tr + i];
#pragma unroll
        for (int j = 0; j < 4; j++) bv[j] = s_B[l * SP + tc + j];
#pragma unroll
        for (int i = 0; i < 4; i++)
#pragma unroll
            for (int j = 0; j < 4; j++) stt[i][j] += xv[i] * bv[j];
    }
    const size_t sbase = (size_t)blk * 4096;
#pragma unroll
    for (int i = 0; i < 4; i++)
#pragma unroll
        for (int j = 0; j < 4; j++)
            g_cs[sbase + (tr + i) * 64 + tc + j] = stt[i][j];
}

// ------------------------- SSD phase 2: inter-chunk scan --------------------
__global__ void __launch_bounds__(256) ssd_phase2() {
    const int bh = blockIdx.x;
    const int tid = threadIdx.x;
    float st[16];
#pragma unroll
    for (int k = 0; k < 16; k++) st[k] = 0.f;
    const size_t b0 = (size_t)bh * NCHUNK * 4096;
    for (int c = 0; c < NCHUNK; c++) {
        const size_t base = b0 + (size_t)c * 4096;
        const float T = g_T[bh * NCHUNK + c];
#pragma unroll
        for (int k = 0; k < 16; k++) {
            g_ps[base + tid + (k << 8)] = st[k];
            st[k] = st[k] * T + g_cs[base + tid + (k << 8)];
        }
    }
}

// ------------------------- SSD phase 3: Y_off -------------------------------
__global__ void __launch_bounds__(256) ssd_phase3() {
    __shared__ float s_C[64 * SP];
    __shared__ float s_S[64 * SP];
    __shared__ float s_el[64];
    const int blk = blockIdx.x;
    const int c = blk & (NCHUNK - 1);
    const int bh = blk >> 6;
    const int b = bh >> 5, h = bh & 31;
    const int tid = threadIdx.x;
    const int tr = (tid >> 4) << 2;
    const int tc = (tid & 15) << 2;
    const int m0 = b * T_LEN + c * CHUNK;

#pragma unroll
    for (int i = 0; i < 16; i++) {
        int idx = tid + (i << 8);
        int l = idx >> 6, q = idx & 63;
        s_C[l * SP + q] =
            g_xbc[(size_t)(m0 + l) * CONV_DIM + D_INNER + D_STATE + q];
        s_S[l * SP + q] = g_ps[(size_t)blk * 4096 + l * 64 + q];
    }
    if (tid < 64) s_el[tid] = g_el[(size_t)blk * 64 + tid];
    __syncthreads();

    float a[4][4] = {};
    for (int n = 0; n < 64; n++) {
        float cv[4], sv[4];
#pragma unroll
        for (int i = 0; i < 4; i++) cv[i] = s_C[(tr + i) * SP + n];
#pragma unroll
        for (int j = 0; j < 4; j++) sv[j] = s_S[(tc + j) * SP + n];
#pragma unroll
        for (int i = 0; i < 4; i++)
#pragma unroll
            for (int j = 0; j < 4; j++) a[i][j] += cv[i] * sv[j];
    }
#pragma unroll
    for (int i = 0; i < 4; i++) {
        const int l = tr + i;
        const float el = s_el[l];
        const size_t orow = (size_t)(m0 + l) * D_INNER + h * HEADDIM;
#pragma unroll
        for (int j = 0; j < 4; j++) g_y[orow + tc + j] += el * a[i][j];
    }
}

// ------------------------- gate + RMSNorm -> bf16 hi/lo ---------------------
__global__ void gate_rms_kernel(const float* __restrict__ norm_w,
                                __nv_bfloat16* __restrict__ yh,
                                __nv_bfloat16* __restrict__ yl) {
    const int m = blockIdx.x;
    const int tid = threadIdx.x;
    const size_t ybase = (size_t)m * D_INNER;
    const size_t zbase = (size_t)m * D_IN_PROJ;
    float vals[8];
    float ssum = 0.f;
#pragma unroll
    for (int i = 0; i < 8; i++) {
        const int idx = tid + i * 256;
        const float yv = g_y[ybase + idx];
        const float z = g_zxbcdt[zbase + idx];
        const float g = yv * z / (1.f + expf(-z));
        vals[i] = g;
        ssum += g * g;
    }
    __shared__ float red[256];
    red[tid] = ssum;
    __syncthreads();
    for (int s = 128; s > 0; s >>= 1) {
        if (tid < s) red[tid] += red[tid + s];
        __syncthreads();
    }
    const float scale = rsqrtf(red[0] / (float)D_INNER + 1e-5f);
#pragma unroll
    for (int i = 0; i < 8; i++) {
        const int idx = tid + i * 256;
        const float v = vals[i] * scale * norm_w[idx];
        const __nv_bfloat16 h = __float2bfloat16(v);
        yh[ybase + idx] = h;
        yl[ybase + idx] = __float2bfloat16(v - __bfloat162float(h));
    }
}

// ---------------------------------------------------------------------------
extern "C" void kernel_launch(void* const* d_in, const int* in_sizes, int n_in,
                              void* d_out, int out_size) {
    const float* u       = (const float*)d_in[0];
    const float* W_in    = (const float*)d_in[1];
    const float* conv_w  = (const float*)d_in[2];
    const float* conv_b  = (const float*)d_in[3];
    const float* dt_bias = (const float*)d_in[4];
    const float* A_log   = (const float*)d_in[5];
    const float* Dv      = (const float*)d_in[6];
    const float* norm_w  = (const float*)d_in[7];
    const float* W_out   = (const float*)d_in[8];
    float* out = (float*)d_out;

    float* zx_p;
    __nv_bfloat16 *uh, *ul, *wih, *wil, *yh, *yl, *woh, *wol;
    cudaGetSymbolAddress((void**)&zx_p, g_zxbcdt);
    cudaGetSymbolAddress((void**)&uh, g_uh);
    cudaGetSymbolAddress((void**)&ul, g_ul);
    cudaGetSymbolAddress((void**)&wih, g_wih);
    cudaGetSymbolAddress((void**)&wil, g_wil);
    cudaGetSymbolAddress((void**)&yh, g_yh);
    cudaGetSymbolAddress((void**)&yl, g_yl);
    cudaGetSymbolAddress((void**)&woh, g_woh);
    cudaGetSymbolAddress((void**)&wol, g_wol);

    cudaFuncSetAttribute(gemm_mma_kernel,
                         cudaFuncAttributeMaxDynamicSharedMemorySize, GEMM_SMEM);
    const int p1_smem = (4 * 64 * SP + 3 * 64) * (int)sizeof(float);
    cudaFuncSetAttribute(ssd_phase1,
                         cudaFuncAttributeMaxDynamicSharedMemorySize, p1_smem);

    // split GEMM1 inputs
    {
        int n = M_TOK * D_MODEL;
        split_kernel<<<(n + 255) / 256, 256>>>(u, uh, ul, n);
        n = D_IN_PROJ * D_MODEL;
        split_kernel<<<(n + 255) / 256, 256>>>(W_in, wih, wil, n);
    }

    // GEMM1: zxbcdt = u @ W_in^T  (8192 x 4256 x 1024)
    gemm_mma_kernel<<<dim3((D_IN_PROJ + 127) / 128, M_TOK / 128), 256,
                      GEMM_SMEM>>>(uh, ul, wih, wil, zx_p,
                                   M_TOK, D_IN_PROJ, D_MODEL);

    dt_kernel<<<(M_TOK * NHEADS) / 256, 256>>>(dt_bias);
    conv_silu_kernel<<<dim3(CONV_DIM / 128, M_TOK), 128>>>(conv_w, conv_b);

    ssd_phase1<<<NBH * NCHUNK, 256, p1_smem>>>(A_log, Dv);
    ssd_phase2<<<NBH, 256>>>();
    ssd_phase3<<<NBH * NCHUNK, 256>>>();

    gate_rms_kernel<<<M_TOK, 256>>>(norm_w, yh, yl);

    // split W_out
    {
        int n = D_MODEL * D_INNER;
        split_kernel<<<(n + 255) / 256, 256>>>(W_out, woh, wol, n);
    }

    // GEMM2: out = y_n @ W_out^T  (8192 x 1024 x 2048)
    gemm_mma_kernel<<<dim3(D_MODEL / 128, M_TOK / 128), 256,
                      GEMM_SMEM>>>(yh, yl, woh, wol, out,
                                   M_TOK, D_MODEL, D_INNER);
}

// round 4
// speedup vs baseline: 4.6304x; 1.1408x over previous
#include <cuda_runtime.h>
#include <cuda_bf16.h>
#include <math.h>
#include <stdint.h>

#define D_MODEL   1024
#define D_STATE   64
#define D_CONV    4
#define D_INNER   2048
#define NHEADS    32
#define HEADDIM   64
#define CHUNK     64
#define CONV_DIM  2176
#define D_IN_PROJ 4256
#define B_SZ      2
#define T_LEN     4096
#define M_TOK     (B_SZ * T_LEN)   // 8192
#define NCHUNK    (T_LEN / CHUNK)  // 64
#define NBH       (B_SZ * NHEADS)  // 64

// ------------------------- scratch (device globals) -------------------------
__device__ float g_zxbcdt[(size_t)M_TOK * D_IN_PROJ];
__device__ float g_xbc[(size_t)M_TOK * CONV_DIM];
__device__ float g_dt[(size_t)M_TOK * NHEADS];
__device__ float g_y[(size_t)M_TOK * D_INNER];

__device__ __nv_bfloat16 g_uh[(size_t)M_TOK * D_MODEL];
__device__ __nv_bfloat16 g_ul[(size_t)M_TOK * D_MODEL];
__device__ __nv_bfloat16 g_wih[(size_t)D_IN_PROJ * D_MODEL];
__device__ __nv_bfloat16 g_wil[(size_t)D_IN_PROJ * D_MODEL];
__device__ __nv_bfloat16 g_yh[(size_t)M_TOK * D_INNER];
__device__ __nv_bfloat16 g_yl[(size_t)M_TOK * D_INNER];
__device__ __nv_bfloat16 g_woh[(size_t)D_MODEL * D_INNER];
__device__ __nv_bfloat16 g_wol[(size_t)D_MODEL * D_INNER];

__device__ float g_cs[(size_t)NBH * NCHUNK * 64 * 64];
__device__ float g_ps[(size_t)NBH * NCHUNK * 64 * 64];
__device__ float g_T[NBH * NCHUNK];
__device__ float g_el[(size_t)NBH * NCHUNK * CHUNK];

// ------------------------- helpers ------------------------------------------
__device__ __forceinline__ uint32_t smem_u32(const void* p) {
    uint32_t a;
    asm("{ .reg .u64 t; cvta.to.shared.u64 t, %1; cvt.u32.u64 %0, t; }"
        : "=r"(a) : "l"(p));
    return a;
}
__device__ __forceinline__ void ldsm_x4(uint32_t& r0, uint32_t& r1,
                                        uint32_t& r2, uint32_t& r3,
                                        uint32_t addr) {
    asm volatile("ldmatrix.sync.aligned.m8n8.x4.shared.b16 {%0,%1,%2,%3}, [%4];"
                 : "=r"(r0), "=r"(r1), "=r"(r2), "=r"(r3) : "r"(addr));
}
__device__ __forceinline__ void ldsm_x4_t(uint32_t& r0, uint32_t& r1,
                                          uint32_t& r2, uint32_t& r3,
                                          uint32_t addr) {
    asm volatile("ldmatrix.sync.aligned.m8n8.x4.trans.shared.b16 {%0,%1,%2,%3}, [%4];"
                 : "=r"(r0), "=r"(r1), "=r"(r2), "=r"(r3) : "r"(addr));
}
__device__ __forceinline__ void mma_bf16(float* c, const uint32_t* a,
                                         uint32_t b0, uint32_t b1) {
    asm volatile(
        "mma.sync.aligned.m16n8k16.row.col.f32.bf16.bf16.f32 "
        "{%0,%1,%2,%3}, {%4,%5,%6,%7}, {%8,%9}, {%0,%1,%2,%3};"
        : "+f"(c[0]), "+f"(c[1]), "+f"(c[2]), "+f"(c[3])
        : "r"(a[0]), "r"(a[1]), "r"(a[2]), "r"(a[3]), "r"(b0), "r"(b1));
}
__device__ __forceinline__ void mma3(float* c, const uint32_t* ah,
                                     const uint32_t* al, const uint32_t* bh,
                                     const uint32_t* bl) {
    mma_bf16(c, ah, bh[0], bh[1]);
    mma_bf16(c, ah, bl[0], bl[1]);
    mma_bf16(c, al, bh[0], bh[1]);
}
__device__ __forceinline__ void cp16(uint32_t dst, const void* src) {
    asm volatile("cp.async.cg.shared.global [%0], [%1], 16;"
                 :: "r"(dst), "l"(src));
}
__device__ __forceinline__ void cp16z(uint32_t dst, const void* src, int valid) {
    int sz = valid ? 16 : 0;
    asm volatile("cp.async.cg.shared.global [%0], [%1], 16, %2;"
                 :: "r"(dst), "l"(src), "r"(sz));
}
#define CP_COMMIT() asm volatile("cp.async.commit_group;" ::: "memory")
#define CP_WAIT(N)  asm volatile("cp.async.wait_group %0;" :: "n"(N) : "memory")

// GEMM smem tile: [128 rows][32 bf16] = 64B/row, 16B chunks XOR-swizzled.
__device__ __forceinline__ uint32_t swz(int row, int kb) {
    return (uint32_t)(row * 64 + ((((kb >> 4) ^ (row & 3)) << 4) | (kb & 15)));
}
// SSD smem tile: [64 rows][64 bf16] = 128B/row, 16B chunks XOR-swizzled.
__device__ __forceinline__ uint32_t swz128(int row, int cb) {
    return (uint32_t)(row * 128 + (cb ^ ((row & 7) << 4)));
}

__device__ __forceinline__ void split2(float v0, float v1,
                                       uint32_t& whi, uint32_t& wlo) {
    __nv_bfloat16 h0 = __float2bfloat16(v0), h1 = __float2bfloat16(v1);
    float r0 = v0 - __bfloat162float(h0), r1 = v1 - __bfloat162float(h1);
    __nv_bfloat162 hh; hh.x = h0; hh.y = h1;
    __nv_bfloat162 ll; ll.x = __float2bfloat16(r0); ll.y = __float2bfloat16(r1);
    whi = *(uint32_t*)&hh;
    wlo = *(uint32_t*)&ll;
}
__device__ __forceinline__ float2 unpack2(uint32_t wh, uint32_t wl) {
    __nv_bfloat162 a = *(__nv_bfloat162*)&wh;
    __nv_bfloat162 b = *(__nv_bfloat162*)&wl;
    return make_float2(__bfloat162float(a.x) + __bfloat162float(b.x),
                       __bfloat162float(a.y) + __bfloat162float(b.y));
}

// ------------------------- split fp32 -> bf16 hi/lo -------------------------
__global__ void split_kernel(const float* __restrict__ src,
                             __nv_bfloat16* __restrict__ hi,
                             __nv_bfloat16* __restrict__ lo, int n) {
    int i = blockIdx.x * 256 + threadIdx.x;
    if (i < n) {
        float v = src[i];
        __nv_bfloat16 h = __float2bfloat16(v);
        hi[i] = h;
        lo[i] = __float2bfloat16(v - __bfloat162float(h));
    }
}

// ------------------------- HMMA GEMM: C[M,N] = A[M,K] @ B[N,K]^T ------------
#define TILE_B   8192
#define STAGE_B  (4 * TILE_B)
#define GEMM_SMEM (2 * STAGE_B)
__global__ void __launch_bounds__(256) gemm_mma_kernel(
    const __nv_bfloat16* __restrict__ Ah, const __nv_bfloat16* __restrict__ Al,
    const __nv_bfloat16* __restrict__ Bh, const __nv_bfloat16* __restrict__ Bl,
    float* __restrict__ C, int M, int N, int K) {
    extern __shared__ char smem[];
    const uint32_t sb = smem_u32(smem);

    const int tid  = threadIdx.x;
    const int wid  = tid >> 5;
    const int lane = tid & 31;
    const int m0 = blockIdx.y << 7;
    const int n0 = blockIdx.x << 7;
    const int wm0 = (wid >> 2) << 6;
    const int wn0 = (wid & 3) << 5;

    const int r0c = tid >> 2, c0c = tid & 3;
    const int r1c = (tid + 256) >> 2, c1c = tid & 3;

    float acc[4][4][4];
#pragma unroll
    for (int f = 0; f < 4; f++)
#pragma unroll
        for (int g = 0; g < 4; g++)
#pragma unroll
            for (int e = 0; e < 4; e++) acc[f][g][e] = 0.f;

    const int nk = K >> 5;

    auto load_stage = [&](int kc, int s) {
        const int k0 = kc << 5;
        const uint32_t st = sb + s * STAGE_B;
        {
            const size_t o0 = (size_t)(m0 + r0c) * K + k0 + c0c * 8;
            const size_t o1 = (size_t)(m0 + r1c) * K + k0 + c1c * 8;
            uint32_t d0 = st + swz(r0c, c0c * 16);
            uint32_t d1 = st + swz(r1c, c1c * 16);
            cp16(d0, Ah + o0);  cp16(d1, Ah + o1);
            cp16(d0 + TILE_B, Al + o0);  cp16(d1 + TILE_B, Al + o1);
        }
        {
            const int v0 = (n0 + r0c) < N, v1 = (n0 + r1c) < N;
            const size_t o0 = v0 ? (size_t)(n0 + r0c) * K + k0 + c0c * 8 : 0;
            const size_t o1 = v1 ? (size_t)(n0 + r1c) * K + k0 + c1c * 8 : 0;
            uint32_t d0 = st + 2 * TILE_B + swz(r0c, c0c * 16);
            uint32_t d1 = st + 2 * TILE_B + swz(r1c, c1c * 16);
            cp16z(d0, Bh + o0, v0);  cp16z(d1, Bh + o1, v1);
            cp16z(d0 + TILE_B, Bl + o0, v0);  cp16z(d1 + TILE_B, Bl + o1, v1);
        }
        CP_COMMIT();
    };

    load_stage(0, 0);

    const int a_row = lane & 15;
    const int a_kb  = (lane >> 4) << 4;
    const int b_row = (lane & 7) + ((lane >> 4) << 3);
    const int b_kb  = ((lane >> 3) & 1) << 4;

    for (int kc = 0; kc < nk; kc++) {
        if (kc + 1 < nk) load_stage(kc + 1, (kc + 1) & 1);
        if (kc + 1 < nk) { CP_WAIT(1); } else { CP_WAIT(0); }
        __syncthreads();

        const uint32_t st  = sb + (kc & 1) * STAGE_B;
        const uint32_t sAh = st, sAl = st + TILE_B;
        const uint32_t sBh = st + 2 * TILE_B, sBl = st + 3 * TILE_B;

#pragma unroll
        for (int kk = 0; kk < 2; kk++) {
            const int kb_a = kk * 32 + a_kb;
            const int kb_b = kk * 32 + b_kb;
            uint32_t ah[4][4], al[4][4], bh[2][4], bl[2][4];
#pragma unroll
            for (int f = 0; f < 4; f++) {
                const int row = wm0 + f * 16 + a_row;
                ldsm_x4(ah[f][0], ah[f][1], ah[f][2], ah[f][3],
                        sAh + swz(row, kb_a));
                ldsm_x4(al[f][0], al[f][1], al[f][2], al[f][3],
                        sAl + swz(row, kb_a));
            }
#pragma unroll
            for (int g2 = 0; g2 < 2; g2++) {
                const int row = wn0 + g2 * 16 + b_row;
                ldsm_x4(bh[g2][0], bh[g2][1], bh[g2][2], bh[g2][3],
                        sBh + swz(row, kb_b));
                ldsm_x4(bl[g2][0], bl[g2][1], bl[g2][2], bl[g2][3],
                        sBl + swz(row, kb_b));
            }
#pragma unroll
            for (int f = 0; f < 4; f++)
#pragma unroll
                for (int g = 0; g < 4; g++) {
                    const uint32_t* bhf = &bh[g >> 1][(g & 1) << 1];
                    const uint32_t* blf = &bl[g >> 1][(g & 1) << 1];
                    mma_bf16(acc[f][g], ah[f], bhf[0], bhf[1]);
                    mma_bf16(acc[f][g], ah[f], blf[0], blf[1]);
                    mma_bf16(acc[f][g], al[f], bhf[0], bhf[1]);
                }
        }
        __syncthreads();
    }

    const int er = lane >> 2;
    const int ec = (lane & 3) << 1;
#pragma unroll
    for (int f = 0; f < 4; f++) {
        const int row = m0 + wm0 + f * 16 + er;
#pragma unroll
        for (int g = 0; g < 4; g++) {
            const int col = n0 + wn0 + g * 8 + ec;
            if (col < N) {
                *(float2*)&C[(size_t)row * N + col] =
                    make_float2(acc[f][g][0], acc[f][g][1]);
                *(float2*)&C[(size_t)(row + 8) * N + col] =
                    make_float2(acc[f][g][2], acc[f][g][3]);
            }
        }
    }
}

// ------------------------- dt = softplus(raw + bias) ------------------------
__global__ void dt_kernel(const float* __restrict__ dt_bias) {
    const int idx = blockIdx.x * 256 + threadIdx.x;
    const int m = idx >> 5;
    const int h = idx & 31;
    float v = g_zxbcdt[(size_t)m * D_IN_PROJ + (D_INNER + CONV_DIM) + h] + dt_bias[h];
    g_dt[idx] = (v > 20.f) ? v : log1pf(expf(v));
}

// ------------------------- depthwise causal conv + SiLU ---------------------
__global__ void conv_silu_kernel(const float* __restrict__ w,
                                 const float* __restrict__ bias) {
    const int c = blockIdx.x * 128 + threadIdx.x;
    const int m = blockIdx.y;
    const int t = m & (T_LEN - 1);
    float acc = bias[c];
#pragma unroll
    for (int j = 0; j < 4; j++) {
        const int tt = t - 3 + j;
        if (tt >= 0)
            acc += w[c * 4 + j] *
                   g_zxbcdt[(size_t)(m - 3 + j) * D_IN_PROJ + D_INNER + c];
    }
    g_xbc[(size_t)m * CONV_DIM + c] = acc / (1.f + expf(-acc));
}

// ------------------------- SSD phase 1 (tensor cores) -----------------------
// smem layout (byte offsets)
#define OFF_XH 0
#define OFF_XL 8192
#define OFF_BH 16384
#define OFF_BL 24576
#define OFF_CH 32768
#define OFF_CL 40960
#define OFF_MH 49152
#define OFF_ML 57344
#define SSD1_SMEM (65536 + 3 * 64 * 4)
__global__ void __launch_bounds__(256) ssd1_tc(const float* __restrict__ A_log,
                                               const float* __restrict__ Dvec) {
    extern __shared__ char sm[];
    const uint32_t sb = smem_u32(sm);
    float* s_cum  = (float*)(sm + 65536);
    float* s_dt   = s_cum + 64;
    float* s_coef = s_dt + 64;

    const int blk = blockIdx.x;
    const int c   = blk & (NCHUNK - 1);
    const int bh  = blk >> 6;
    const int b = bh >> 5, h = bh & 31;
    const int tid = threadIdx.x, wid = tid >> 5, lane = tid & 31;
    const int r0 = (wid & 3) * 16, c0 = (wid >> 2) * 32;
    const int m0 = b * T_LEN + c * CHUNK;
    const float Ahc = -expf(A_log[h]);
    const float Dh  = Dvec[h];

    // ---- load & split x, B, C into bf16 hi/lo tiles ----
#pragma unroll
    for (int i = 0; i < 8; i++) {
        int flat = tid + (i << 8);
        int l = flat >> 5, q2 = flat & 31;
        const size_t row = (size_t)(m0 + l) * CONV_DIM;
        float2 vx = *(const float2*)&g_xbc[row + h * HEADDIM + q2 * 2];
        float2 vb = *(const float2*)&g_xbc[row + D_INNER + q2 * 2];
        float2 vc = *(const float2*)&g_xbc[row + D_INNER + D_STATE + q2 * 2];
        uint32_t so = swz128(l, q2 * 4);
        uint32_t wh, wl;
        split2(vx.x, vx.y, wh, wl);
        *(uint32_t*)(sm + OFF_XH + so) = wh;
        *(uint32_t*)(sm + OFF_XL + so) = wl;
        split2(vb.x, vb.y, wh, wl);
        *(uint32_t*)(sm + OFF_BH + so) = wh;
        *(uint32_t*)(sm + OFF_BL + so) = wl;
        split2(vc.x, vc.y, wh, wl);
        *(uint32_t*)(sm + OFF_CH + so) = wh;
        *(uint32_t*)(sm + OFF_CL + so) = wl;
    }
    if (tid < 64) s_dt[tid] = g_dt[(size_t)(m0 + tid) * NHEADS + h];
    __syncthreads();
    if (tid == 0) {
        float cum = 0.f;
        for (int l = 0; l < 64; l++) { cum += Ahc * s_dt[l]; s_cum[l] = cum; }
    }
    __syncthreads();
    if (tid < 64) {
        s_coef[tid] = s_dt[tid] * __expf(s_cum[63] - s_cum[tid]);
        g_el[(size_t)blk * 64 + tid] = __expf(s_cum[tid]);
    }
    if (tid == 0) g_T[blk] = __expf(s_cum[63]);
    __syncthreads();

    const int er = lane >> 2, ec = (lane & 3) << 1;

    // ---- step A: G = C @ B^T, mask/decay -> M (bf16 split) ----
    {
        float acc[4][4];
#pragma unroll
        for (int g = 0; g < 4; g++)
#pragma unroll
            for (int e = 0; e < 4; e++) acc[g][e] = 0.f;
#pragma unroll
        for (int k16 = 0; k16 < 4; k16++) {
            uint32_t ah[4], al[4];
            uint32_t aoff = swz128(r0 + (lane & 15),
                                   k16 * 32 + ((lane >> 4) << 4));
            ldsm_x4(ah[0], ah[1], ah[2], ah[3], sb + OFF_CH + aoff);
            ldsm_x4(al[0], al[1], al[2], al[3], sb + OFF_CL + aoff);
            uint32_t bhf[2][4], blf[2][4];
#pragma unroll
            for (int g2 = 0; g2 < 2; g2++) {
                uint32_t boff =
                    swz128(c0 + g2 * 16 + (lane & 7) + ((lane >> 4) << 3),
                           k16 * 32 + (((lane >> 3) & 1) << 4));
                ldsm_x4(bhf[g2][0], bhf[g2][1], bhf[g2][2], bhf[g2][3],
                        sb + OFF_BH + boff);
                ldsm_x4(blf[g2][0], blf[g2][1], blf[g2][2], blf[g2][3],
                        sb + OFF_BL + boff);
            }
#pragma unroll
            for (int g = 0; g < 4; g++)
                mma3(acc[g], ah, al, &bhf[g >> 1][(g & 1) << 1],
                     &blf[g >> 1][(g & 1) << 1]);
        }
#pragma unroll
        for (int g = 0; g < 4; g++) {
            int s0 = c0 + g * 8 + ec;
            float cs0 = s_cum[s0], cs1 = s_cum[s0 + 1];
            float d0 = s_dt[s0], d1 = s_dt[s0 + 1];
#pragma unroll
            for (int hf = 0; hf < 2; hf++) {
                int l = r0 + er + hf * 8;
                float cl = s_cum[l];
                float v0 = (s0     <= l) ? acc[g][hf * 2 + 0] * __expf(cl - cs0) * d0 : 0.f;
                float v1 = (s0 + 1 <= l) ? acc[g][hf * 2 + 1] * __expf(cl - cs1) * d1 : 0.f;
                uint32_t wh, wl;
                split2(v0, v1, wh, wl);
                uint32_t so = swz128(l, s0 * 2);
                *(uint32_t*)(sm + OFF_MH + so) = wh;
                *(uint32_t*)(sm + OFF_ML + so) = wl;
            }
        }
    }
    __syncthreads();

    // ---- CX = coef(l) * x  (overwrites C tiles) ----
#pragma unroll
    for (int i = 0; i < 8; i++) {
        int flat = tid + (i << 8);
        int l = flat >> 5, q2 = flat & 31;
        uint32_t so = swz128(l, q2 * 4);
        float2 v = unpack2(*(uint32_t*)(sm + OFF_XH + so),
                           *(uint32_t*)(sm + OFF_XL + so));
        float cf = s_coef[l];
        uint32_t oh, ol;
        split2(v.x * cf, v.y * cf, oh, ol);
        *(uint32_t*)(sm + OFF_CH + so) = oh;
        *(uint32_t*)(sm + OFF_CL + so) = ol;
    }

    // ---- step B: Y = M @ x (+ D skip), write g_y ----
    {
        float acc[4][4];
#pragma unroll
        for (int g = 0; g < 4; g++)
#pragma unroll
            for (int e = 0; e < 4; e++) acc[g][e] = 0.f;
#pragma unroll
        for (int k16 = 0; k16 < 4; k16++) {
            uint32_t ah[4], al[4];
            uint32_t aoff = swz128(r0 + (lane & 15),
                                   k16 * 32 + ((lane >> 4) << 4));
            ldsm_x4(ah[0], ah[1], ah[2], ah[3], sb + OFF_MH + aoff);
            ldsm_x4(al[0], al[1], al[2], al[3], sb + OFF_ML + aoff);
            uint32_t bhf[2][4], blf[2][4];
#pragma unroll
            for (int g2 = 0; g2 < 2; g2++) {
                uint32_t boff =
                    swz128(k16 * 16 + ((lane >> 3) & 1) * 8 + (lane & 7),
                           (c0 + g2 * 16) * 2 + (((lane >> 4) & 1) << 4));
                ldsm_x4_t(bhf[g2][0], bhf[g2][1], bhf[g2][2], bhf[g2][3],
                          sb + OFF_XH + boff);
                ldsm_x4_t(blf[g2][0], blf[g2][1], blf[g2][2], blf[g2][3],
                          sb + OFF_XL + boff);
            }
#pragma unroll
            for (int g = 0; g < 4; g++)
                mma3(acc[g], ah, al, &bhf[g >> 1][(g & 1) << 1],
                     &blf[g >> 1][(g & 1) << 1]);
        }
#pragma unroll
        for (int g = 0; g < 4; g++) {
            int p0 = c0 + g * 8 + ec;
#pragma unroll
            for (int hf = 0; hf < 2; hf++) {
                int l = r0 + er + hf * 8;
                uint32_t so = swz128(l, p0 * 2);
                float2 xv = unpack2(*(uint32_t*)(sm + OFF_XH + so),
                                    *(uint32_t*)(sm + OFF_XL + so));
                *(float2*)&g_y[(size_t)(m0 + l) * D_INNER + h * HEADDIM + p0] =
                    make_float2(acc[g][hf * 2 + 0] + Dh * xv.x,
                                acc[g][hf * 2 + 1] + Dh * xv.y);
            }
        }
    }
    __syncthreads();

    // ---- step C: S(p,n) = CX^T @ B, write g_cs ----
    {
        float acc[4][4];
#pragma unroll
        for (int g = 0; g < 4; g++)
#pragma unroll
            for (int e = 0; e < 4; e++) acc[g][e] = 0.f;
#pragma unroll
        for (int k16 = 0; k16 < 4; k16++) {
            uint32_t ah[4], al[4];
            uint32_t aoff =
                swz128(k16 * 16 + ((lane >> 4) & 1) * 8 + (lane & 7),
                       r0 * 2 + (((lane >> 3) & 1) << 4));
            ldsm_x4_t(ah[0], ah[1], ah[2], ah[3], sb + OFF_CH + aoff);
            ldsm_x4_t(al[0], al[1], al[2], al[3], sb + OFF_CL + aoff);
            uint32_t bhf[2][4], blf[2][4];
#pragma unroll
            for (int g2 = 0; g2 < 2; g2++) {
                uint32_t boff =
                    swz128(k16 * 16 + ((lane >> 3) & 1) * 8 + (lane & 7),
                           (c0 + g2 * 16) * 2 + (((lane >> 4) & 1) << 4));
                ldsm_x4_t(bhf[g2][0], bhf[g2][1], bhf[g2][2], bhf[g2][3],
                          sb + OFF_BH + boff);
                ldsm_x4_t(blf[g2][0], blf[g2][1], blf[g2][2], blf[g2][3],
                          sb + OFF_BL + boff);
            }
#pragma unroll
            for (int g = 0; g < 4; g++)
                mma3(acc[g], ah, al, &bhf[g >> 1][(g & 1) << 1],
                     &blf[g >> 1][(g & 1) << 1]);
        }
        const size_t sbase = (size_t)blk * 4096;
#pragma unroll
        for (int g = 0; g < 4; g++) {
            int n0 = c0 + g * 8 + ec;
#pragma unroll
            for (int hf = 0; hf < 2; hf++) {
                int p = r0 + er + hf * 8;
                *(float2*)&g_cs[sbase + p * 64 + n0] =
                    make_float2(acc[g][hf * 2 + 0], acc[g][hf * 2 + 1]);
            }
        }
    }
}

// ------------------------- SSD phase 2: inter-chunk scan --------------------
__global__ void __launch_bounds__(256) ssd_phase2() {
    const int bh = blockIdx.x;
    const int tid = threadIdx.x;
    float st[16];
#pragma unroll
    for (int k = 0; k < 16; k++) st[k] = 0.f;
    const size_t b0 = (size_t)bh * NCHUNK * 4096;
    for (int c = 0; c < NCHUNK; c++) {
        const size_t base = b0 + (size_t)c * 4096;
        const float T = g_T[bh * NCHUNK + c];
#pragma unroll
        for (int k = 0; k < 16; k++) {
            g_ps[base + tid + (k << 8)] = st[k];
            st[k] = st[k] * T + g_cs[base + tid + (k << 8)];
        }
    }
}

// ------------------------- SSD phase 3 (tensor cores): Y += el * C @ S^T ----
__global__ void __launch_bounds__(256) ssd3_tc() {
    __shared__ char t_Ch[8192], t_Cl[8192], t_Sh[8192], t_Sl[8192];
    __shared__ float s_el[64];
    const uint32_t aCh = smem_u32(t_Ch), aCl = smem_u32(t_Cl);
    const uint32_t aSh = smem_u32(t_Sh), aSl = smem_u32(t_Sl);

    const int blk = blockIdx.x;
    const int c   = blk & (NCHUNK - 1);
    const int bh  = blk >> 6;
    const int b = bh >> 5, h = bh & 31;
    const int tid = threadIdx.x, wid = tid >> 5, lane = tid & 31;
    const int r0 = (wid & 3) * 16, c0 = (wid >> 2) * 32;
    const int m0 = b * T_LEN + c * CHUNK;

#pragma unroll
    for (int i = 0; i < 8; i++) {
        int flat = tid + (i << 8);
        int l = flat >> 5, q2 = flat & 31;
        uint32_t so = swz128(l, q2 * 4);
        float2 vc = *(const float2*)&g_xbc[(size_t)(m0 + l) * CONV_DIM +
                                           D_INNER + D_STATE + q2 * 2];
        uint32_t wh, wl;
        split2(vc.x, vc.y, wh, wl);
        *(uint32_t*)(t_Ch + so) = wh;
        *(uint32_t*)(t_Cl + so) = wl;
        float2 vs = *(const float2*)&g_ps[(size_t)blk * 4096 + l * 64 + q2 * 2];
        split2(vs.x, vs.y, wh, wl);
        *(uint32_t*)(t_Sh + so) = wh;
        *(uint32_t*)(t_Sl + so) = wl;
    }
    if (tid < 64) s_el[tid] = g_el[(size_t)blk * 64 + tid];
    __syncthreads();

    float acc[4][4];
#pragma unroll
    for (int g = 0; g < 4; g++)
#pragma unroll
        for (int e = 0; e < 4; e++) acc[g][e] = 0.f;
#pragma unroll
    for (int k16 = 0; k16 < 4; k16++) {
        uint32_t ah[4], al[4];
        uint32_t aoff = swz128(r0 + (lane & 15), k16 * 32 + ((lane >> 4) << 4));
        ldsm_x4(ah[0], ah[1], ah[2], ah[3], aCh + aoff);
        ldsm_x4(al[0], al[1], al[2], al[3], aCl + aoff);
        uint32_t bhf[2][4], blf[2][4];
#pragma unroll
        for (int g2 = 0; g2 < 2; g2++) {
            uint32_t boff =
                swz128(c0 + g2 * 16 + (lane & 7) + ((lane >> 4) << 3),
                       k16 * 32 + (((lane >> 3) & 1) << 4));
            ldsm_x4(bhf[g2][0], bhf[g2][1], bhf[g2][2], bhf[g2][3], aSh + boff);
            ldsm_x4(blf[g2][0], blf[g2][1], blf[g2][2], blf[g2][3], aSl + boff);
        }
#pragma unroll
        for (int g = 0; g < 4; g++)
            mma3(acc[g], ah, al, &bhf[g >> 1][(g & 1) << 1],
                 &blf[g >> 1][(g & 1) << 1]);
    }
    const int er = lane >> 2, ec = (lane & 3) << 1;
#pragma unroll
    for (int g = 0; g < 4; g++) {
        int p0 = c0 + g * 8 + ec;
#pragma unroll
        for (int hf = 0; hf < 2; hf++) {
            int l = r0 + er + hf * 8;
            float el = s_el[l];
            float2* yp =
                (float2*)&g_y[(size_t)(m0 + l) * D_INNER + h * HEADDIM + p0];
            float2 cur = *yp;
            cur.x += el * acc[g][hf * 2 + 0];
            cur.y += el * acc[g][hf * 2 + 1];
            *yp = cur;
        }
    }
}

// ------------------------- gate + RMSNorm -> bf16 hi/lo ---------------------
__global__ void gate_rms_kernel(const float* __restrict__ norm_w,
                                __nv_bfloat16* __restrict__ yh,
                                __nv_bfloat16* __restrict__ yl) {
    const int m = blockIdx.x;
    const int tid = threadIdx.x;
    const size_t ybase = (size_t)m * D_INNER;
    const size_t zbase = (size_t)m * D_IN_PROJ;
    float vals[8];
    float ssum = 0.f;
#pragma unroll
    for (int i = 0; i < 8; i++) {
        const int idx = tid + i * 256;
        const float yv = g_y[ybase + idx];
        const float z = g_zxbcdt[zbase + idx];
        const float g = yv * z / (1.f + expf(-z));
        vals[i] = g;
        ssum += g * g;
    }
    __shared__ float red[256];
    red[tid] = ssum;
    __syncthreads();
    for (int s = 128; s > 0; s >>= 1) {
        if (tid < s) red[tid] += red[tid + s];
        __syncthreads();
    }
    const float scale = rsqrtf(red[0] / (float)D_INNER + 1e-5f);
#pragma unroll
    for (int i = 0; i < 8; i++) {
        const int idx = tid + i * 256;
        const float v = vals[i] * scale * norm_w[idx];
        const __nv_bfloat16 h = __float2bfloat16(v);
        yh[ybase + idx] = h;
        yl[ybase + idx] = __float2bfloat16(v - __bfloat162float(h));
    }
}

// ---------------------------------------------------------------------------
extern "C" void kernel_launch(void* const* d_in, const int* in_sizes, int n_in,
                              void* d_out, int out_size) {
    const float* u       = (const float*)d_in[0];
    const float* W_in    = (const float*)d_in[1];
    const float* conv_w  = (const float*)d_in[2];
    const float* conv_b  = (const float*)d_in[3];
    const float* dt_bias = (const float*)d_in[4];
    const float* A_log   = (const float*)d_in[5];
    const float* Dv      = (const float*)d_in[6];
    const float* norm_w  = (const float*)d_in[7];
    const float* W_out   = (const float*)d_in[8];
    float* out = (float*)d_out;

    float* zx_p;
    __nv_bfloat16 *uh, *ul, *wih, *wil, *yh, *yl, *woh, *wol;
    cudaGetSymbolAddress((void**)&zx_p, g_zxbcdt);
    cudaGetSymbolAddress((void**)&uh, g_uh);
    cudaGetSymbolAddress((void**)&ul, g_ul);
    cudaGetSymbolAddress((void**)&wih, g_wih);
    cudaGetSymbolAddress((void**)&wil, g_wil);
    cudaGetSymbolAddress((void**)&yh, g_yh);
    cudaGetSymbolAddress((void**)&yl, g_yl);
    cudaGetSymbolAddress((void**)&woh, g_woh);
    cudaGetSymbolAddress((void**)&wol, g_wol);

    cudaFuncSetAttribute(gemm_mma_kernel,
                         cudaFuncAttributeMaxDynamicSharedMemorySize, GEMM_SMEM);
    cudaFuncSetAttribute(ssd1_tc,
                         cudaFuncAttributeMaxDynamicSharedMemorySize, SSD1_SMEM);

    {
        int n = M_TOK * D_MODEL;
        split_kernel<<<(n + 255) / 256, 256>>>(u, uh, ul, n);
        n = D_IN_PROJ * D_MODEL;
        split_kernel<<<(n + 255) / 256, 256>>>(W_in, wih, wil, n);
    }

    gemm_mma_kernel<<<dim3((D_IN_PROJ + 127) / 128, M_TOK / 128), 256,
                      GEMM_SMEM>>>(uh, ul, wih, wil, zx_p,
                                   M_TOK, D_IN_PROJ, D_MODEL);

    dt_kernel<<<(M_TOK * NHEADS) / 256, 256>>>(dt_bias);
    conv_silu_kernel<<<dim3(CONV_DIM / 128, M_TOK), 128>>>(conv_w, conv_b);

    ssd1_tc<<<NBH * NCHUNK, 256, SSD1_SMEM>>>(A_log, Dv);
    ssd_phase2<<<NBH, 256>>>();
    ssd3_tc<<<NBH * NCHUNK, 256>>>();

    gate_rms_kernel<<<M_TOK, 256>>>(norm_w, yh, yl);

    {
        int n = D_MODEL * D_INNER;
        split_kernel<<<(n + 255) / 256, 256>>>(W_out, woh, wol, n);
    }

    gemm_mma_kernel<<<dim3(D_MODEL / 128, M_TOK / 128), 256,
                      GEMM_SMEM>>>(yh, yl, woh, wol, out,
                                   M_TOK, D_MODEL, D_INNER);
}

// round 5
// speedup vs baseline: 4.6822x; 1.0112x over previous
#include <cuda_runtime.h>
#include <cuda_bf16.h>
#include <math.h>
#include <stdint.h>

#define D_MODEL   1024
#define D_STATE   64
#define D_CONV    4
#define D_INNER   2048
#define NHEADS    32
#define HEADDIM   64
#define CHUNK     64
#define CONV_DIM  2176
#define D_IN_PROJ 4256
#define B_SZ      2
#define T_LEN     4096
#define M_TOK     (B_SZ * T_LEN)   // 8192
#define NCHUNK    (T_LEN / CHUNK)  // 64
#define NBH       (B_SZ * NHEADS)  // 64

// ------------------------- scratch (device globals) -------------------------
__device__ float g_zxbcdt[(size_t)M_TOK * D_IN_PROJ];
__device__ float g_xbc[(size_t)M_TOK * CONV_DIM];
__device__ float g_dt[(size_t)M_TOK * NHEADS];
__device__ float g_y[(size_t)M_TOK * D_INNER];

__device__ __nv_bfloat16 g_uh[(size_t)M_TOK * D_MODEL];
__device__ __nv_bfloat16 g_ul[(size_t)M_TOK * D_MODEL];
__device__ __nv_bfloat16 g_wih[(size_t)D_IN_PROJ * D_MODEL];
__device__ __nv_bfloat16 g_wil[(size_t)D_IN_PROJ * D_MODEL];
__device__ __nv_bfloat16 g_yh[(size_t)M_TOK * D_INNER];
__device__ __nv_bfloat16 g_yl[(size_t)M_TOK * D_INNER];
__device__ __nv_bfloat16 g_woh[(size_t)D_MODEL * D_INNER];
__device__ __nv_bfloat16 g_wol[(size_t)D_MODEL * D_INNER];

__device__ float g_cs[(size_t)NBH * NCHUNK * 64 * 64];
__device__ float g_ps[(size_t)NBH * NCHUNK * 64 * 64];
__device__ float g_T[NBH * NCHUNK];
__device__ float g_el[(size_t)NBH * NCHUNK * CHUNK];

// ------------------------- helpers ------------------------------------------
__device__ __forceinline__ uint32_t smem_u32(const void* p) {
    uint32_t a;
    asm("{ .reg .u64 t; cvta.to.shared.u64 t, %1; cvt.u32.u64 %0, t; }"
        : "=r"(a) : "l"(p));
    return a;
}
__device__ __forceinline__ void ldsm_x4(uint32_t& r0, uint32_t& r1,
                                        uint32_t& r2, uint32_t& r3,
                                        uint32_t addr) {
    asm volatile("ldmatrix.sync.aligned.m8n8.x4.shared.b16 {%0,%1,%2,%3}, [%4];"
                 : "=r"(r0), "=r"(r1), "=r"(r2), "=r"(r3) : "r"(addr));
}
__device__ __forceinline__ void ldsm_x4_t(uint32_t& r0, uint32_t& r1,
                                          uint32_t& r2, uint32_t& r3,
                                          uint32_t addr) {
    asm volatile("ldmatrix.sync.aligned.m8n8.x4.trans.shared.b16 {%0,%1,%2,%3}, [%4];"
                 : "=r"(r0), "=r"(r1), "=r"(r2), "=r"(r3) : "r"(addr));
}
__device__ __forceinline__ void mma_bf16(float* c, const uint32_t* a,
                                         uint32_t b0, uint32_t b1) {
    asm volatile(
        "mma.sync.aligned.m16n8k16.row.col.f32.bf16.bf16.f32 "
        "{%0,%1,%2,%3}, {%4,%5,%6,%7}, {%8,%9}, {%0,%1,%2,%3};"
        : "+f"(c[0]), "+f"(c[1]), "+f"(c[2]), "+f"(c[3])
        : "r"(a[0]), "r"(a[1]), "r"(a[2]), "r"(a[3]), "r"(b0), "r"(b1));
}
__device__ __forceinline__ void mma3(float* c, const uint32_t* ah,
                                     const uint32_t* al, const uint32_t* bh,
                                     const uint32_t* bl) {
    mma_bf16(c, ah, bh[0], bh[1]);
    mma_bf16(c, ah, bl[0], bl[1]);
    mma_bf16(c, al, bh[0], bh[1]);
}
__device__ __forceinline__ void cp16(uint32_t dst, const void* src) {
    asm volatile("cp.async.cg.shared.global [%0], [%1], 16;"
                 :: "r"(dst), "l"(src));
}
__device__ __forceinline__ void cp16z(uint32_t dst, const void* src, int valid) {
    int sz = valid ? 16 : 0;
    asm volatile("cp.async.cg.shared.global [%0], [%1], 16, %2;"
                 :: "r"(dst), "l"(src), "r"(sz));
}
#define CP_COMMIT() asm volatile("cp.async.commit_group;" ::: "memory")
#define CP_WAIT(N)  asm volatile("cp.async.wait_group %0;" :: "n"(N) : "memory")

// GEMM smem tile: [128 rows][32 bf16] = 64B/row, 16B chunks XOR-swizzled.
__device__ __forceinline__ uint32_t swz(int row, int kb) {
    return (uint32_t)(row * 64 + ((((kb >> 4) ^ (row & 3)) << 4) | (kb & 15)));
}
// SSD smem tile: [64 rows][64 bf16] = 128B/row, 16B chunks XOR-swizzled.
__device__ __forceinline__ uint32_t swz128(int row, int cb) {
    return (uint32_t)(row * 128 + (cb ^ ((row & 7) << 4)));
}

__device__ __forceinline__ void split2(float v0, float v1,
                                       uint32_t& whi, uint32_t& wlo) {
    __nv_bfloat16 h0 = __float2bfloat16(v0), h1 = __float2bfloat16(v1);
    float r0 = v0 - __bfloat162float(h0), r1 = v1 - __bfloat162float(h1);
    __nv_bfloat162 hh; hh.x = h0; hh.y = h1;
    __nv_bfloat162 ll; ll.x = __float2bfloat16(r0); ll.y = __float2bfloat16(r1);
    whi = *(uint32_t*)&hh;
    wlo = *(uint32_t*)&ll;
}
__device__ __forceinline__ float2 unpack2(uint32_t wh, uint32_t wl) {
    __nv_bfloat162 a = *(__nv_bfloat162*)&wh;
    __nv_bfloat162 b = *(__nv_bfloat162*)&wl;
    return make_float2(__bfloat162float(a.x) + __bfloat162float(b.x),
                       __bfloat162float(a.y) + __bfloat162float(b.y));
}

// ------------------------- split fp32 -> bf16 hi/lo -------------------------
__global__ void split_kernel(const float* __restrict__ src,
                             __nv_bfloat16* __restrict__ hi,
                             __nv_bfloat16* __restrict__ lo, int n) {
    int i = blockIdx.x * 256 + threadIdx.x;
    if (i < n) {
        float v = src[i];
        __nv_bfloat16 h = __float2bfloat16(v);
        hi[i] = h;
        lo[i] = __float2bfloat16(v - __bfloat162float(h));
    }
}

// ------------------------- HMMA GEMM: C[M,N] = A[M,K] @ B[N,K]^T ------------
// 3-stage cp.async pipeline.
#define TILE_B   8192
#define STAGE_B  (4 * TILE_B)
#define NSTAGE   3
#define GEMM_SMEM (NSTAGE * STAGE_B)   // 96 KB
__global__ void __launch_bounds__(256) gemm_mma_kernel(
    const __nv_bfloat16* __restrict__ Ah, const __nv_bfloat16* __restrict__ Al,
    const __nv_bfloat16* __restrict__ Bh, const __nv_bfloat16* __restrict__ Bl,
    float* __restrict__ C, int M, int N, int K) {
    extern __shared__ char smem[];
    const uint32_t sb = smem_u32(smem);

    const int tid  = threadIdx.x;
    const int wid  = tid >> 5;
    const int lane = tid & 31;
    const int m0 = blockIdx.y << 7;
    const int n0 = blockIdx.x << 7;
    const int wm0 = (wid >> 2) << 6;
    const int wn0 = (wid & 3) << 5;

    const int r0c = tid >> 2, c0c = tid & 3;
    const int r1c = (tid + 256) >> 2, c1c = tid & 3;

    float acc[4][4][4];
#pragma unroll
    for (int f = 0; f < 4; f++)
#pragma unroll
        for (int g = 0; g < 4; g++)
#pragma unroll
            for (int e = 0; e < 4; e++) acc[f][g][e] = 0.f;

    const int nk = K >> 5;

    auto load_stage = [&](int kc, int s) {
        const int k0 = kc << 5;
        const uint32_t st = sb + s * STAGE_B;
        {
            const size_t o0 = (size_t)(m0 + r0c) * K + k0 + c0c * 8;
            const size_t o1 = (size_t)(m0 + r1c) * K + k0 + c1c * 8;
            uint32_t d0 = st + swz(r0c, c0c * 16);
            uint32_t d1 = st + swz(r1c, c1c * 16);
            cp16(d0, Ah + o0);  cp16(d1, Ah + o1);
            cp16(d0 + TILE_B, Al + o0);  cp16(d1 + TILE_B, Al + o1);
        }
        {
            const int v0 = (n0 + r0c) < N, v1 = (n0 + r1c) < N;
            const size_t o0 = v0 ? (size_t)(n0 + r0c) * K + k0 + c0c * 8 : 0;
            const size_t o1 = v1 ? (size_t)(n0 + r1c) * K + k0 + c1c * 8 : 0;
            uint32_t d0 = st + 2 * TILE_B + swz(r0c, c0c * 16);
            uint32_t d1 = st + 2 * TILE_B + swz(r1c, c1c * 16);
            cp16z(d0, Bh + o0, v0);  cp16z(d1, Bh + o1, v1);
            cp16z(d0 + TILE_B, Bl + o0, v0);  cp16z(d1 + TILE_B, Bl + o1, v1);
        }
        CP_COMMIT();
    };

    load_stage(0, 0);
    load_stage(1, 1);

    const int a_row = lane & 15;
    const int a_kb  = (lane >> 4) << 4;
    const int b_row = (lane & 7) + ((lane >> 4) << 3);
    const int b_kb  = ((lane >> 3) & 1) << 4;

    int stage = 0;
    for (int kc = 0; kc < nk; kc++) {
        CP_WAIT(1);
        __syncthreads();
        if (kc + 2 < nk) {
            int ns = stage + 2;
            if (ns >= NSTAGE) ns -= NSTAGE;
            load_stage(kc + 2, ns);
        }

        const uint32_t st  = sb + stage * STAGE_B;
        const uint32_t sAh = st, sAl = st + TILE_B;
        const uint32_t sBh = st + 2 * TILE_B, sBl = st + 3 * TILE_B;

#pragma unroll
        for (int kk = 0; kk < 2; kk++) {
            const int kb_a = kk * 32 + a_kb;
            const int kb_b = kk * 32 + b_kb;
            uint32_t ah[4][4], al[4][4], bh[2][4], bl[2][4];
#pragma unroll
            for (int f = 0; f < 4; f++) {
                const int row = wm0 + f * 16 + a_row;
                ldsm_x4(ah[f][0], ah[f][1], ah[f][2], ah[f][3],
                        sAh + swz(row, kb_a));
                ldsm_x4(al[f][0], al[f][1], al[f][2], al[f][3],
                        sAl + swz(row, kb_a));
            }
#pragma unroll
            for (int g2 = 0; g2 < 2; g2++) {
                const int row = wn0 + g2 * 16 + b_row;
                ldsm_x4(bh[g2][0], bh[g2][1], bh[g2][2], bh[g2][3],
                        sBh + swz(row, kb_b));
                ldsm_x4(bl[g2][0], bl[g2][1], bl[g2][2], bl[g2][3],
                        sBl + swz(row, kb_b));
            }
#pragma unroll
            for (int f = 0; f < 4; f++)
#pragma unroll
                for (int g = 0; g < 4; g++) {
                    const uint32_t* bhf = &bh[g >> 1][(g & 1) << 1];
                    const uint32_t* blf = &bl[g >> 1][(g & 1) << 1];
                    mma_bf16(acc[f][g], ah[f], bhf[0], bhf[1]);
                    mma_bf16(acc[f][g], ah[f], blf[0], blf[1]);
                    mma_bf16(acc[f][g], al[f], bhf[0], bhf[1]);
                }
        }
        __syncthreads();
        if (++stage == NSTAGE) stage = 0;
    }

    const int er = lane >> 2;
    const int ec = (lane & 3) << 1;
#pragma unroll
    for (int f = 0; f < 4; f++) {
        const int row = m0 + wm0 + f * 16 + er;
#pragma unroll
        for (int g = 0; g < 4; g++) {
            const int col = n0 + wn0 + g * 8 + ec;
            if (col < N) {
                *(float2*)&C[(size_t)row * N + col] =
                    make_float2(acc[f][g][0], acc[f][g][1]);
                *(float2*)&C[(size_t)(row + 8) * N + col] =
                    make_float2(acc[f][g][2], acc[f][g][3]);
            }
        }
    }
}

// ------------------------- dt = softplus(raw + bias) ------------------------
__global__ void dt_kernel(const float* __restrict__ dt_bias) {
    const int idx = blockIdx.x * 256 + threadIdx.x;
    const int m = idx >> 5;
    const int h = idx & 31;
    float v = g_zxbcdt[(size_t)m * D_IN_PROJ + (D_INNER + CONV_DIM) + h] + dt_bias[h];
    g_dt[idx] = (v > 20.f) ? v : log1pf(expf(v));
}

// ------------------------- tiled depthwise conv + SiLU ----------------------
// block: 128 channels x 64 tokens; smem tile 67 x 128 floats.
__global__ void __launch_bounds__(256) conv_silu_kernel(
    const float* __restrict__ w, const float* __restrict__ bias) {
    __shared__ float sx[67][128];
    const int cb = blockIdx.x;            // 0..16 channel tile
    const int tb = blockIdx.y;            // 0..127 token tile
    const int tid = threadIdx.x;
    const int m0 = tb * 64;               // flat token base
    const int zero_head = ((m0 & (T_LEN - 1)) == 0);

    // load rows: row i holds token m0 - 3 + i
    for (int idx = tid; idx < 67 * 128; idx += 256) {
        const int r = idx >> 7, ch = idx & 127;
        float v = 0.f;
        if (r >= 3 || !zero_head)
            v = g_zxbcdt[(size_t)(m0 - 3 + r) * D_IN_PROJ + D_INNER +
                         cb * 128 + ch];
        sx[r][ch] = v;
    }
    __syncthreads();

    const int ch = tid & 127;
    const int th = (tid >> 7) * 32;       // 0 or 32: token half
    const int gc = cb * 128 + ch;
    const float w0 = w[gc * 4 + 0], w1 = w[gc * 4 + 1];
    const float w2 = w[gc * 4 + 2], w3 = w[gc * 4 + 3];
    const float bz = bias[gc];
#pragma unroll 8
    for (int i = 0; i < 32; i++) {
        const int t = th + i;
        float acc = bz + w0 * sx[t][ch] + w1 * sx[t + 1][ch] +
                    w2 * sx[t + 2][ch] + w3 * sx[t + 3][ch];
        g_xbc[(size_t)(m0 + t) * CONV_DIM + gc] = acc / (1.f + expf(-acc));
    }
}

// ------------------------- SSD phase 1 (tensor cores) -----------------------
#define OFF_XH 0
#define OFF_XL 8192
#define OFF_BH 16384
#define OFF_BL 24576
#define OFF_CH 32768
#define OFF_CL 40960
#define OFF_MH 49152
#define OFF_ML 57344
#define SSD1_SMEM (65536 + 3 * 64 * 4)
__global__ void __launch_bounds__(256) ssd1_tc(const float* __restrict__ A_log,
                                               const float* __restrict__ Dvec) {
    extern __shared__ char sm[];
    const uint32_t sb = smem_u32(sm);
    float* s_cum  = (float*)(sm + 65536);
    float* s_dt   = s_cum + 64;
    float* s_coef = s_dt + 64;

    const int blk = blockIdx.x;
    const int c   = blk & (NCHUNK - 1);
    const int bh  = blk >> 6;
    const int b = bh >> 5, h = bh & 31;
    const int tid = threadIdx.x, wid = tid >> 5, lane = tid & 31;
    const int r0 = (wid & 3) * 16, c0 = (wid >> 2) * 32;
    const int m0 = b * T_LEN + c * CHUNK;
    const float Ahc = -expf(A_log[h]);
    const float Dh  = Dvec[h];

#pragma unroll
    for (int i = 0; i < 8; i++) {
        int flat = tid + (i << 8);
        int l = flat >> 5, q2 = flat & 31;
        const size_t row = (size_t)(m0 + l) * CONV_DIM;
        float2 vx = *(const float2*)&g_xbc[row + h * HEADDIM + q2 * 2];
        float2 vb = *(const float2*)&g_xbc[row + D_INNER + q2 * 2];
        float2 vc = *(const float2*)&g_xbc[row + D_INNER + D_STATE + q2 * 2];
        uint32_t so = swz128(l, q2 * 4);
        uint32_t wh, wl;
        split2(vx.x, vx.y, wh, wl);
        *(uint32_t*)(sm + OFF_XH + so) = wh;
        *(uint32_t*)(sm + OFF_XL + so) = wl;
        split2(vb.x, vb.y, wh, wl);
        *(uint32_t*)(sm + OFF_BH + so) = wh;
        *(uint32_t*)(sm + OFF_BL + so) = wl;
        split2(vc.x, vc.y, wh, wl);
        *(uint32_t*)(sm + OFF_CH + so) = wh;
        *(uint32_t*)(sm + OFF_CL + so) = wl;
    }
    if (tid < 64) s_dt[tid] = g_dt[(size_t)(m0 + tid) * NHEADS + h];
    __syncthreads();
    // warp-scan cumsum over 64 (warp 0, 2 values per lane)
    if (wid == 0) {
        float v0 = Ahc * s_dt[lane * 2], v1 = Ahc * s_dt[lane * 2 + 1];
        float s = v0 + v1;
#pragma unroll
        for (int o = 1; o < 32; o <<= 1) {
            float t = __shfl_up_sync(0xFFFFFFFF, s, o);
            if (lane >= o) s += t;
        }
        float excl = s - (v0 + v1);
        s_cum[lane * 2] = excl + v0;
        s_cum[lane * 2 + 1] = excl + v0 + v1;
    }
    __syncthreads();
    if (tid < 64) {
        s_coef[tid] = s_dt[tid] * __expf(s_cum[63] - s_cum[tid]);
        g_el[(size_t)blk * 64 + tid] = __expf(s_cum[tid]);
    }
    if (tid == 0) g_T[blk] = __expf(s_cum[63]);
    __syncthreads();

    const int er = lane >> 2, ec = (lane & 3) << 1;

    // ---- step A: G = C @ B^T, mask/decay -> M ----
    {
        float acc[4][4];
#pragma unroll
        for (int g = 0; g < 4; g++)
#pragma unroll
            for (int e = 0; e < 4; e++) acc[g][e] = 0.f;
#pragma unroll
        for (int k16 = 0; k16 < 4; k16++) {
            uint32_t ah[4], al[4];
            uint32_t aoff = swz128(r0 + (lane & 15),
                                   k16 * 32 + ((lane >> 4) << 4));
            ldsm_x4(ah[0], ah[1], ah[2], ah[3], sb + OFF_CH + aoff);
            ldsm_x4(al[0], al[1], al[2], al[3], sb + OFF_CL + aoff);
            uint32_t bhf[2][4], blf[2][4];
#pragma unroll
            for (int g2 = 0; g2 < 2; g2++) {
                uint32_t boff =
                    swz128(c0 + g2 * 16 + (lane & 7) + ((lane >> 4) << 3),
                           k16 * 32 + (((lane >> 3) & 1) << 4));
                ldsm_x4(bhf[g2][0], bhf[g2][1], bhf[g2][2], bhf[g2][3],
                        sb + OFF_BH + boff);
                ldsm_x4(blf[g2][0], blf[g2][1], blf[g2][2], blf[g2][3],
                        sb + OFF_BL + boff);
            }
#pragma unroll
            for (int g = 0; g < 4; g++)
                mma3(acc[g], ah, al, &bhf[g >> 1][(g & 1) << 1],
                     &blf[g >> 1][(g & 1) << 1]);
        }
#pragma unroll
        for (int g = 0; g < 4; g++) {
            int s0 = c0 + g * 8 + ec;
            float cs0 = s_cum[s0], cs1 = s_cum[s0 + 1];
            float d0 = s_dt[s0], d1 = s_dt[s0 + 1];
#pragma unroll
            for (int hf = 0; hf < 2; hf++) {
                int l = r0 + er + hf * 8;
                float cl = s_cum[l];
                float v0 = (s0     <= l) ? acc[g][hf * 2 + 0] * __expf(cl - cs0) * d0 : 0.f;
                float v1 = (s0 + 1 <= l) ? acc[g][hf * 2 + 1] * __expf(cl - cs1) * d1 : 0.f;
                uint32_t wh, wl;
                split2(v0, v1, wh, wl);
                uint32_t so = swz128(l, s0 * 2);
                *(uint32_t*)(sm + OFF_MH + so) = wh;
                *(uint32_t*)(sm + OFF_ML + so) = wl;
            }
        }
    }
    __syncthreads();

    // ---- CX = coef(l) * x ----
#pragma unroll
    for (int i = 0; i < 8; i++) {
        int flat = tid + (i << 8);
        int l = flat >> 5, q2 = flat & 31;
        uint32_t so = swz128(l, q2 * 4);
        float2 v = unpack2(*(uint32_t*)(sm + OFF_XH + so),
                           *(uint32_t*)(sm + OFF_XL + so));
        float cf = s_coef[l];
        uint32_t oh, ol;
        split2(v.x * cf, v.y * cf, oh, ol);
        *(uint32_t*)(sm + OFF_CH + so) = oh;
        *(uint32_t*)(sm + OFF_CL + so) = ol;
    }

    // ---- step B: Y = M @ x (+ D skip) ----
    {
        float acc[4][4];
#pragma unroll
        for (int g = 0; g < 4; g++)
#pragma unroll
            for (int e = 0; e < 4; e++) acc[g][e] = 0.f;
#pragma unroll
        for (int k16 = 0; k16 < 4; k16++) {
            uint32_t ah[4], al[4];
            uint32_t aoff = swz128(r0 + (lane & 15),
                                   k16 * 32 + ((lane >> 4) << 4));
            ldsm_x4(ah[0], ah[1], ah[2], ah[3], sb + OFF_MH + aoff);
            ldsm_x4(al[0], al[1], al[2], al[3], sb + OFF_ML + aoff);
            uint32_t bhf[2][4], blf[2][4];
#pragma unroll
            for (int g2 = 0; g2 < 2; g2++) {
                uint32_t boff =
                    swz128(k16 * 16 + ((lane >> 3) & 1) * 8 + (lane & 7),
                           (c0 + g2 * 16) * 2 + (((lane >> 4) & 1) << 4));
                ldsm_x4_t(bhf[g2][0], bhf[g2][1], bhf[g2][2], bhf[g2][3],
                          sb + OFF_XH + boff);
                ldsm_x4_t(blf[g2][0], blf[g2][1], blf[g2][2], blf[g2][3],
                          sb + OFF_XL + boff);
            }
#pragma unroll
            for (int g = 0; g < 4; g++)
                mma3(acc[g], ah, al, &bhf[g >> 1][(g & 1) << 1],
                     &blf[g >> 1][(g & 1) << 1]);
        }
#pragma unroll
        for (int g = 0; g < 4; g++) {
            int p0 = c0 + g * 8 + ec;
#pragma unroll
            for (int hf = 0; hf < 2; hf++) {
                int l = r0 + er + hf * 8;
                uint32_t so = swz128(l, p0 * 2);
                float2 xv = unpack2(*(uint32_t*)(sm + OFF_XH + so),
                                    *(uint32_t*)(sm + OFF_XL + so));
                *(float2*)&g_y[(size_t)(m0 + l) * D_INNER + h * HEADDIM + p0] =
                    make_float2(acc[g][hf * 2 + 0] + Dh * xv.x,
                                acc[g][hf * 2 + 1] + Dh * xv.y);
            }
        }
    }
    __syncthreads();

    // ---- step C: S(p,n) = CX^T @ B ----
    {
        float acc[4][4];
#pragma unroll
        for (int g = 0; g < 4; g++)
#pragma unroll
            for (int e = 0; e < 4; e++) acc[g][e] = 0.f;
#pragma unroll
        for (int k16 = 0; k16 < 4; k16++) {
            uint32_t ah[4], al[4];
            uint32_t aoff =
                swz128(k16 * 16 + ((lane >> 4) & 1) * 8 + (lane & 7),
                       r0 * 2 + (((lane >> 3) & 1) << 4));
            ldsm_x4_t(ah[0], ah[1], ah[2], ah[3], sb + OFF_CH + aoff);
            ldsm_x4_t(al[0], al[1], al[2], al[3], sb + OFF_CL + aoff);
            uint32_t bhf[2][4], blf[2][4];
#pragma unroll
            for (int g2 = 0; g2 < 2; g2++) {
                uint32_t boff =
                    swz128(k16 * 16 + ((lane >> 3) & 1) * 8 + (lane & 7),
                           (c0 + g2 * 16) * 2 + (((lane >> 4) & 1) << 4));
                ldsm_x4_t(bhf[g2][0], bhf[g2][1], bhf[g2][2], bhf[g2][3],
                          sb + OFF_BH + boff);
                ldsm_x4_t(blf[g2][0], blf[g2][1], blf[g2][2], blf[g2][3],
                          sb + OFF_BL + boff);
            }
#pragma unroll
            for (int g = 0; g < 4; g++)
                mma3(acc[g], ah, al, &bhf[g >> 1][(g & 1) << 1],
                     &blf[g >> 1][(g & 1) << 1]);
        }
        const size_t sbase = (size_t)blk * 4096;
#pragma unroll
        for (int g = 0; g < 4; g++) {
            int n0 = c0 + g * 8 + ec;
#pragma unroll
            for (int hf = 0; hf < 2; hf++) {
                int p = r0 + er + hf * 8;
                *(float2*)&g_cs[sbase + p * 64 + n0] =
                    make_float2(acc[g][hf * 2 + 0], acc[g][hf * 2 + 1]);
            }
        }
    }
}

// ------------------------- SSD phase 2: inter-chunk scan (16x parallel) -----
__global__ void __launch_bounds__(256) ssd_phase2() {
    const int slice = blockIdx.x & 15;
    const int bh    = blockIdx.x >> 4;
    const int off   = slice * 256 + threadIdx.x;
    float st = 0.f;
    const size_t b0 = (size_t)bh * NCHUNK * 4096;
    const float* Tp = &g_T[bh * NCHUNK];
#pragma unroll 4
    for (int c = 0; c < NCHUNK; c++) {
        const size_t base = b0 + (size_t)c * 4096 + off;
        g_ps[base] = st;
        st = st * Tp[c] + g_cs[base];
    }
}

// ------------------------- SSD phase 3 (tensor cores) -----------------------
__global__ void __launch_bounds__(256) ssd3_tc() {
    __shared__ char t_Ch[8192], t_Cl[8192], t_Sh[8192], t_Sl[8192];
    __shared__ float s_el[64];
    const uint32_t aCh = smem_u32(t_Ch), aCl = smem_u32(t_Cl);
    const uint32_t aSh = smem_u32(t_Sh), aSl = smem_u32(t_Sl);

    const int blk = blockIdx.x;
    const int c   = blk & (NCHUNK - 1);
    const int bh  = blk >> 6;
    const int b = bh >> 5, h = bh & 31;
    const int tid = threadIdx.x, wid = tid >> 5, lane = tid & 31;
    const int r0 = (wid & 3) * 16, c0 = (wid >> 2) * 32;
    const int m0 = b * T_LEN + c * CHUNK;

#pragma unroll
    for (int i = 0; i < 8; i++) {
        int flat = tid + (i << 8);
        int l = flat >> 5, q2 = flat & 31;
        uint32_t so = swz128(l, q2 * 4);
        float2 vc = *(const float2*)&g_xbc[(size_t)(m0 + l) * CONV_DIM +
                                           D_INNER + D_STATE + q2 * 2];
        uint32_t wh, wl;
        split2(vc.x, vc.y, wh, wl);
        *(uint32_t*)(t_Ch + so) = wh;
        *(uint32_t*)(t_Cl + so) = wl;
        float2 vs = *(const float2*)&g_ps[(size_t)blk * 4096 + l * 64 + q2 * 2];
        split2(vs.x, vs.y, wh, wl);
        *(uint32_t*)(t_Sh + so) = wh;
        *(uint32_t*)(t_Sl + so) = wl;
    }
    if (tid < 64) s_el[tid] = g_el[(size_t)blk * 64 + tid];
    __syncthreads();

    float acc[4][4];
#pragma unroll
    for (int g = 0; g < 4; g++)
#pragma unroll
        for (int e = 0; e < 4; e++) acc[g][e] = 0.f;
#pragma unroll
    for (int k16 = 0; k16 < 4; k16++) {
        uint32_t ah[4], al[4];
        uint32_t aoff = swz128(r0 + (lane & 15), k16 * 32 + ((lane >> 4) << 4));
        ldsm_x4(ah[0], ah[1], ah[2], ah[3], aCh + aoff);
        ldsm_x4(al[0], al[1], al[2], al[3], aCl + aoff);
        uint32_t bhf[2][4], blf[2][4];
#pragma unroll
        for (int g2 = 0; g2 < 2; g2++) {
            uint32_t boff =
                swz128(c0 + g2 * 16 + (lane & 7) + ((lane >> 4) << 3),
                       k16 * 32 + (((lane >> 3) & 1) << 4));
            ldsm_x4(bhf[g2][0], bhf[g2][1], bhf[g2][2], bhf[g2][3], aSh + boff);
            ldsm_x4(blf[g2][0], blf[g2][1], blf[g2][2], blf[g2][3], aSl + boff);
        }
#pragma unroll
        for (int g = 0; g < 4; g++)
            mma3(acc[g], ah, al, &bhf[g >> 1][(g & 1) << 1],
                 &blf[g >> 1][(g & 1) << 1]);
    }
    const int er = lane >> 2, ec = (lane & 3) << 1;
#pragma unroll
    for (int g = 0; g < 4; g++) {
        int p0 = c0 + g * 8 + ec;
#pragma unroll
        for (int hf = 0; hf < 2; hf++) {
            int l = r0 + er + hf * 8;
            float el = s_el[l];
            float2* yp =
                (float2*)&g_y[(size_t)(m0 + l) * D_INNER + h * HEADDIM + p0];
            float2 cur = *yp;
            cur.x += el * acc[g][hf * 2 + 0];
            cur.y += el * acc[g][hf * 2 + 1];
            *yp = cur;
        }
    }
}

// ------------------------- gate + RMSNorm -> bf16 hi/lo ---------------------
__global__ void gate_rms_kernel(const float* __restrict__ norm_w,
                                __nv_bfloat16* __restrict__ yh,
                                __nv_bfloat16* __restrict__ yl) {
    const int m = blockIdx.x;
    const int tid = threadIdx.x;
    const size_t ybase = (size_t)m * D_INNER;
    const size_t zbase = (size_t)m * D_IN_PROJ;
    float vals[8];
    float ssum = 0.f;
#pragma unroll
    for (int i = 0; i < 8; i++) {
        const int idx = tid + i * 256;
        const float yv = g_y[ybase + idx];
        const float z = g_zxbcdt[zbase + idx];
        const float g = yv * z / (1.f + expf(-z));
        vals[i] = g;
        ssum += g * g;
    }
    __shared__ float red[256];
    red[tid] = ssum;
    __syncthreads();
    for (int s = 128; s > 0; s >>= 1) {
        if (tid < s) red[tid] += red[tid + s];
        __syncthreads();
    }
    const float scale = rsqrtf(red[0] / (float)D_INNER + 1e-5f);
#pragma unroll
    for (int i = 0; i < 8; i++) {
        const int idx = tid + i * 256;
        const float v = vals[i] * scale * norm_w[idx];
        const __nv_bfloat16 h = __float2bfloat16(v);
        yh[ybase + idx] = h;
        yl[ybase + idx] = __float2bfloat16(v - __bfloat162float(h));
    }
}

// ---------------------------------------------------------------------------
extern "C" void kernel_launch(void* const* d_in, const int* in_sizes, int n_in,
                              void* d_out, int out_size) {
    const float* u       = (const float*)d_in[0];
    const float* W_in    = (const float*)d_in[1];
    const float* conv_w  = (const float*)d_in[2];
    const float* conv_b  = (const float*)d_in[3];
    const float* dt_bias = (const float*)d_in[4];
    const float* A_log   = (const float*)d_in[5];
    const float* Dv      = (const float*)d_in[6];
    const float* norm_w  = (const float*)d_in[7];
    const float* W_out   = (const float*)d_in[8];
    float* out = (float*)d_out;

    float* zx_p;
    __nv_bfloat16 *uh, *ul, *wih, *wil, *yh, *yl, *woh, *wol;
    cudaGetSymbolAddress((void**)&zx_p, g_zxbcdt);
    cudaGetSymbolAddress((void**)&uh, g_uh);
    cudaGetSymbolAddress((void**)&ul, g_ul);
    cudaGetSymbolAddress((void**)&wih, g_wih);
    cudaGetSymbolAddress((void**)&wil, g_wil);
    cudaGetSymbolAddress((void**)&yh, g_yh);
    cudaGetSymbolAddress((void**)&yl, g_yl);
    cudaGetSymbolAddress((void**)&woh, g_woh);
    cudaGetSymbolAddress((void**)&wol, g_wol);

    cudaFuncSetAttribute(gemm_mma_kernel,
                         cudaFuncAttributeMaxDynamicSharedMemorySize, GEMM_SMEM);
    cudaFuncSetAttribute(ssd1_tc,
                         cudaFuncAttributeMaxDynamicSharedMemorySize, SSD1_SMEM);

    {
        int n = M_TOK * D_MODEL;
        split_kernel<<<(n + 255) / 256, 256>>>(u, uh, ul, n);
        n = D_IN_PROJ * D_MODEL;
        split_kernel<<<(n + 255) / 256, 256>>>(W_in, wih, wil, n);
    }

    gemm_mma_kernel<<<dim3((D_IN_PROJ + 127) / 128, M_TOK / 128), 256,
                      GEMM_SMEM>>>(uh, ul, wih, wil, zx_p,
                                   M_TOK, D_IN_PROJ, D_MODEL);

    dt_kernel<<<(M_TOK * NHEADS) / 256, 256>>>(dt_bias);
    conv_silu_kernel<<<dim3(CONV_DIM / 128, M_TOK / 64), 256>>>(conv_w, conv_b);

    ssd1_tc<<<NBH * NCHUNK, 256, SSD1_SMEM>>>(A_log, Dv);
    ssd_phase2<<<NBH * 16, 256>>>();
    ssd3_tc<<<NBH * NCHUNK, 256>>>();

    gate_rms_kernel<<<M_TOK, 256>>>(norm_w, yh, yl);

    {
        int n = D_MODEL * D_INNER;
        split_kernel<<<(n + 255) / 256, 256>>>(W_out, woh, wol, n);
    }

    gemm_mma_kernel<<<dim3(D_MODEL / 128, M_TOK / 128), 256,
                      GEMM_SMEM>>>(yh, yl, woh, wol, out,
                                   M_TOK, D_MODEL, D_INNER);
}

// round 6
// speedup vs baseline: 8.6420x; 1.8457x over previous
#include <cuda_runtime.h>
#include <cuda_bf16.h>
#include <cuda_fp16.h>
#include <math.h>
#include <stdint.h>

#define D_MODEL   1024
#define D_STATE   64
#define D_CONV    4
#define D_INNER   2048
#define NHEADS    32
#define HEADDIM   64
#define CHUNK     64
#define CONV_DIM  2176
#define D_IN_PROJ 4256
#define B_SZ      2
#define T_LEN     4096
#define M_TOK     (B_SZ * T_LEN)   // 8192
#define NCHUNK    (T_LEN / CHUNK)  // 64
#define NBH       (B_SZ * NHEADS)  // 64

// ------------------------- scratch (device globals) -------------------------
__device__ float g_zxbcdt[(size_t)M_TOK * D_IN_PROJ];
__device__ float g_xbc[(size_t)M_TOK * CONV_DIM];
__device__ float g_dt[(size_t)M_TOK * NHEADS];
__device__ float g_y[(size_t)M_TOK * D_INNER];

__device__ __half g_uh[(size_t)M_TOK * D_MODEL];
__device__ __half g_wih[(size_t)D_IN_PROJ * D_MODEL];
__device__ __half g_yh[(size_t)M_TOK * D_INNER];
__device__ __half g_woh[(size_t)D_MODEL * D_INNER];

__device__ float g_cs[(size_t)NBH * NCHUNK * 64 * 64];
__device__ float g_ps[(size_t)NBH * NCHUNK * 64 * 64];
__device__ float g_T[NBH * NCHUNK];
__device__ float g_el[(size_t)NBH * NCHUNK * CHUNK];

// ------------------------- helpers ------------------------------------------
__device__ __forceinline__ uint32_t smem_u32(const void* p) {
    uint32_t a;
    asm("{ .reg .u64 t; cvta.to.shared.u64 t, %1; cvt.u32.u64 %0, t; }"
        : "=r"(a) : "l"(p));
    return a;
}
__device__ __forceinline__ void ldsm_x4(uint32_t& r0, uint32_t& r1,
                                        uint32_t& r2, uint32_t& r3,
                                        uint32_t addr) {
    asm volatile("ldmatrix.sync.aligned.m8n8.x4.shared.b16 {%0,%1,%2,%3}, [%4];"
                 : "=r"(r0), "=r"(r1), "=r"(r2), "=r"(r3) : "r"(addr));
}
__device__ __forceinline__ void ldsm_x4_t(uint32_t& r0, uint32_t& r1,
                                          uint32_t& r2, uint32_t& r3,
                                          uint32_t addr) {
    asm volatile("ldmatrix.sync.aligned.m8n8.x4.trans.shared.b16 {%0,%1,%2,%3}, [%4];"
                 : "=r"(r0), "=r"(r1), "=r"(r2), "=r"(r3) : "r"(addr));
}
__device__ __forceinline__ void mma_bf16(float* c, const uint32_t* a,
                                         uint32_t b0, uint32_t b1) {
    asm volatile(
        "mma.sync.aligned.m16n8k16.row.col.f32.bf16.bf16.f32 "
        "{%0,%1,%2,%3}, {%4,%5,%6,%7}, {%8,%9}, {%0,%1,%2,%3};"
        : "+f"(c[0]), "+f"(c[1]), "+f"(c[2]), "+f"(c[3])
        : "r"(a[0]), "r"(a[1]), "r"(a[2]), "r"(a[3]), "r"(b0), "r"(b1));
}
__device__ __forceinline__ void mma_fp16(float* c, const uint32_t* a,
                                         uint32_t b0, uint32_t b1) {
    asm volatile(
        "mma.sync.aligned.m16n8k16.row.col.f32.f16.f16.f32 "
        "{%0,%1,%2,%3}, {%4,%5,%6,%7}, {%8,%9}, {%0,%1,%2,%3};"
        : "+f"(c[0]), "+f"(c[1]), "+f"(c[2]), "+f"(c[3])
        : "r"(a[0]), "r"(a[1]), "r"(a[2]), "r"(a[3]), "r"(b0), "r"(b1));
}
__device__ __forceinline__ void mma3(float* c, const uint32_t* ah,
                                     const uint32_t* al, const uint32_t* bh,
                                     const uint32_t* bl) {
    mma_bf16(c, ah, bh[0], bh[1]);
    mma_bf16(c, ah, bl[0], bl[1]);
    mma_bf16(c, al, bh[0], bh[1]);
}
__device__ __forceinline__ void cp16(uint32_t dst, const void* src) {
    asm volatile("cp.async.cg.shared.global [%0], [%1], 16;"
                 :: "r"(dst), "l"(src));
}
__device__ __forceinline__ void cp16z(uint32_t dst, const void* src, int valid) {
    int sz = valid ? 16 : 0;
    asm volatile("cp.async.cg.shared.global [%0], [%1], 16, %2;"
                 :: "r"(dst), "l"(src), "r"(sz));
}
#define CP_COMMIT() asm volatile("cp.async.commit_group;" ::: "memory")
#define CP_WAIT(N)  asm volatile("cp.async.wait_group %0;" :: "n"(N) : "memory")

// GEMM smem tile: [128 rows][32 halves] = 64B/row, XOR-swizzled 16B chunks.
__device__ __forceinline__ uint32_t swz(int row, int kb) {
    return (uint32_t)(row * 64 + ((((kb >> 4) ^ (row & 3)) << 4) | (kb & 15)));
}
// SSD smem tile: [64 rows][64 bf16] = 128B/row, XOR-swizzled.
__device__ __forceinline__ uint32_t swz128(int row, int cb) {
    return (uint32_t)(row * 128 + (cb ^ ((row & 7) << 4)));
}

__device__ __forceinline__ void split2(float v0, float v1,
                                       uint32_t& whi, uint32_t& wlo) {
    __nv_bfloat16 h0 = __float2bfloat16(v0), h1 = __float2bfloat16(v1);
    float r0 = v0 - __bfloat162float(h0), r1 = v1 - __bfloat162float(h1);
    __nv_bfloat162 hh; hh.x = h0; hh.y = h1;
    __nv_bfloat162 ll; ll.x = __float2bfloat16(r0); ll.y = __float2bfloat16(r1);
    whi = *(uint32_t*)&hh;
    wlo = *(uint32_t*)&ll;
}
__device__ __forceinline__ float2 unpack2(uint32_t wh, uint32_t wl) {
    __nv_bfloat162 a = *(__nv_bfloat162*)&wh;
    __nv_bfloat162 b = *(__nv_bfloat162*)&wl;
    return make_float2(__bfloat162float(a.x) + __bfloat162float(b.x),
                       __bfloat162float(a.y) + __bfloat162float(b.y));
}

// ------------------------- fp32 -> fp16 convert -----------------------------
__global__ void cvt_kernel(const float* __restrict__ src,
                           __half* __restrict__ dst, int n) {
    int i = blockIdx.x * 256 + threadIdx.x;
    if (i * 2 < n) {
        float2 v = *(const float2*)(src + i * 2);
        __half2 h; h.x = __float2half_rn(v.x); h.y = __float2half_rn(v.y);
        *(__half2*)(dst + i * 2) = h;
    }
}

// ------------------------- HMMA GEMM (fp16): C = A @ B^T --------------------
// BM=BN=128, BK=32, 8 warps, 4-stage cp.async pipeline, 16KB/stage.
#define TILE_B   8192
#define STAGE_B  (2 * TILE_B)
#define NSTAGE   4
#define GEMM_SMEM (NSTAGE * STAGE_B)   // 64 KB
__global__ void __launch_bounds__(256) gemm_mma_kernel(
    const __half* __restrict__ A, const __half* __restrict__ B,
    float* __restrict__ C, int M, int N, int K) {
    extern __shared__ char smem[];
    const uint32_t sb = smem_u32(smem);

    const int tid  = threadIdx.x;
    const int wid  = tid >> 5;
    const int lane = tid & 31;
    const int m0 = blockIdx.y << 7;
    const int n0 = blockIdx.x << 7;
    const int wm0 = (wid >> 2) << 6;
    const int wn0 = (wid & 3) << 5;

    const int r0c = tid >> 2, c0c = tid & 3;
    const int r1c = (tid + 256) >> 2, c1c = tid & 3;

    float acc[4][4][4];
#pragma unroll
    for (int f = 0; f < 4; f++)
#pragma unroll
        for (int g = 0; g < 4; g++)
#pragma unroll
            for (int e = 0; e < 4; e++) acc[f][g][e] = 0.f;

    const int nk = K >> 5;

    auto load_stage = [&](int kc, int s) {
        const int k0 = kc << 5;
        const uint32_t st = sb + s * STAGE_B;
        {
            const size_t o0 = (size_t)(m0 + r0c) * K + k0 + c0c * 8;
            const size_t o1 = (size_t)(m0 + r1c) * K + k0 + c1c * 8;
            cp16(st + swz(r0c, c0c * 16), A + o0);
            cp16(st + swz(r1c, c1c * 16), A + o1);
        }
        {
            const int v0 = (n0 + r0c) < N, v1 = (n0 + r1c) < N;
            const size_t o0 = v0 ? (size_t)(n0 + r0c) * K + k0 + c0c * 8 : 0;
            const size_t o1 = v1 ? (size_t)(n0 + r1c) * K + k0 + c1c * 8 : 0;
            cp16z(st + TILE_B + swz(r0c, c0c * 16), B + o0, v0);
            cp16z(st + TILE_B + swz(r1c, c1c * 16), B + o1, v1);
        }
        CP_COMMIT();
    };

    load_stage(0, 0);
    load_stage(1, 1);
    load_stage(2, 2);

    const int a_row = lane & 15;
    const int a_kb  = (lane >> 4) << 4;
    const int b_row = (lane & 7) + ((lane >> 4) << 3);
    const int b_kb  = ((lane >> 3) & 1) << 4;

    for (int kc = 0; kc < nk; kc++) {
        CP_WAIT(2);
        __syncthreads();
        if (kc + 3 < nk) load_stage(kc + 3, (kc + 3) & 3);
        else CP_COMMIT();

        const uint32_t st = sb + (kc & 3) * STAGE_B;
        const uint32_t sA = st, sB = st + TILE_B;

#pragma unroll
        for (int kk = 0; kk < 2; kk++) {
            const int kb_a = kk * 32 + a_kb;
            const int kb_b = kk * 32 + b_kb;
            uint32_t ah[4][4], bh[2][4];
#pragma unroll
            for (int f = 0; f < 4; f++) {
                const int row = wm0 + f * 16 + a_row;
                ldsm_x4(ah[f][0], ah[f][1], ah[f][2], ah[f][3],
                        sA + swz(row, kb_a));
            }
#pragma unroll
            for (int g2 = 0; g2 < 2; g2++) {
                const int row = wn0 + g2 * 16 + b_row;
                ldsm_x4(bh[g2][0], bh[g2][1], bh[g2][2], bh[g2][3],
                        sB + swz(row, kb_b));
            }
#pragma unroll
            for (int f = 0; f < 4; f++)
#pragma unroll
                for (int g = 0; g < 4; g++) {
                    const uint32_t* bf = &bh[g >> 1][(g & 1) << 1];
                    mma_fp16(acc[f][g], ah[f], bf[0], bf[1]);
                }
        }
    }

    const int er = lane >> 2;
    const int ec = (lane & 3) << 1;
#pragma unroll
    for (int f = 0; f < 4; f++) {
        const int row = m0 + wm0 + f * 16 + er;
#pragma unroll
        for (int g = 0; g < 4; g++) {
            const int col = n0 + wn0 + g * 8 + ec;
            if (col < N) {
                *(float2*)&C[(size_t)row * N + col] =
                    make_float2(acc[f][g][0], acc[f][g][1]);
                *(float2*)&C[(size_t)(row + 8) * N + col] =
                    make_float2(acc[f][g][2], acc[f][g][3]);
            }
        }
    }
}

// ------------------------- dt = softplus(raw + bias) ------------------------
__global__ void dt_kernel(const float* __restrict__ dt_bias) {
    const int idx = blockIdx.x * 256 + threadIdx.x;
    const int m = idx >> 5;
    const int h = idx & 31;
    float v = g_zxbcdt[(size_t)m * D_IN_PROJ + (D_INNER + CONV_DIM) + h] + dt_bias[h];
    g_dt[idx] = (v > 20.f) ? v : log1pf(expf(v));
}

// ------------------------- tiled depthwise conv + SiLU ----------------------
__global__ void __launch_bounds__(256) conv_silu_kernel(
    const float* __restrict__ w, const float* __restrict__ bias) {
    __shared__ float sx[67][128];
    const int cb = blockIdx.x;
    const int tb = blockIdx.y;
    const int tid = threadIdx.x;
    const int m0 = tb * 64;
    const int zero_head = ((m0 & (T_LEN - 1)) == 0);

    for (int idx = tid; idx < 67 * 128; idx += 256) {
        const int r = idx >> 7, ch = idx & 127;
        float v = 0.f;
        if (r >= 3 || !zero_head)
            v = g_zxbcdt[(size_t)(m0 - 3 + r) * D_IN_PROJ + D_INNER +
                         cb * 128 + ch];
        sx[r][ch] = v;
    }
    __syncthreads();

    const int ch = tid & 127;
    const int th = (tid >> 7) * 32;
    const int gc = cb * 128 + ch;
    const float w0 = w[gc * 4 + 0], w1 = w[gc * 4 + 1];
    const float w2 = w[gc * 4 + 2], w3 = w[gc * 4 + 3];
    const float bz = bias[gc];
#pragma unroll 8
    for (int i = 0; i < 32; i++) {
        const int t = th + i;
        float acc = bz + w0 * sx[t][ch] + w1 * sx[t + 1][ch] +
                    w2 * sx[t + 2][ch] + w3 * sx[t + 3][ch];
        g_xbc[(size_t)(m0 + t) * CONV_DIM + gc] = acc / (1.f + expf(-acc));
    }
}

// ------------------------- SSD phase 1 (tensor cores, bf16x3) ---------------
#define OFF_XH 0
#define OFF_XL 8192
#define OFF_BH 16384
#define OFF_BL 24576
#define OFF_CH 32768
#define OFF_CL 40960
#define OFF_MH 49152
#define OFF_ML 57344
#define SSD1_SMEM (65536 + 3 * 64 * 4)
__global__ void __launch_bounds__(256) ssd1_tc(const float* __restrict__ A_log,
                                               const float* __restrict__ Dvec) {
    extern __shared__ char sm[];
    const uint32_t sb = smem_u32(sm);
    float* s_cum  = (float*)(sm + 65536);
    float* s_dt   = s_cum + 64;
    float* s_coef = s_dt + 64;

    const int blk = blockIdx.x;
    const int c   = blk & (NCHUNK - 1);
    const int bh  = blk >> 6;
    const int b = bh >> 5, h = bh & 31;
    const int tid = threadIdx.x, wid = tid >> 5, lane = tid & 31;
    const int r0 = (wid & 3) * 16, c0 = (wid >> 2) * 32;
    const int m0 = b * T_LEN + c * CHUNK;
    const float Ahc = -expf(A_log[h]);
    const float Dh  = Dvec[h];

#pragma unroll
    for (int i = 0; i < 8; i++) {
        int flat = tid + (i << 8);
        int l = flat >> 5, q2 = flat & 31;
        const size_t row = (size_t)(m0 + l) * CONV_DIM;
        float2 vx = *(const float2*)&g_xbc[row + h * HEADDIM + q2 * 2];
        float2 vb = *(const float2*)&g_xbc[row + D_INNER + q2 * 2];
        float2 vc = *(const float2*)&g_xbc[row + D_INNER + D_STATE + q2 * 2];
        uint32_t so = swz128(l, q2 * 4);
        uint32_t wh, wl;
        split2(vx.x, vx.y, wh, wl);
        *(uint32_t*)(sm + OFF_XH + so) = wh;
        *(uint32_t*)(sm + OFF_XL + so) = wl;
        split2(vb.x, vb.y, wh, wl);
        *(uint32_t*)(sm + OFF_BH + so) = wh;
        *(uint32_t*)(sm + OFF_BL + so) = wl;
        split2(vc.x, vc.y, wh, wl);
        *(uint32_t*)(sm + OFF_CH + so) = wh;
        *(uint32_t*)(sm + OFF_CL + so) = wl;
    }
    if (tid < 64) s_dt[tid] = g_dt[(size_t)(m0 + tid) * NHEADS + h];
    __syncthreads();
    if (wid == 0) {
        float v0 = Ahc * s_dt[lane * 2], v1 = Ahc * s_dt[lane * 2 + 1];
        float s = v0 + v1;
#pragma unroll
        for (int o = 1; o < 32; o <<= 1) {
            float t = __shfl_up_sync(0xFFFFFFFF, s, o);
            if (lane >= o) s += t;
        }
        float excl = s - (v0 + v1);
        s_cum[lane * 2] = excl + v0;
        s_cum[lane * 2 + 1] = excl + v0 + v1;
    }
    __syncthreads();
    if (tid < 64) {
        s_coef[tid] = s_dt[tid] * __expf(s_cum[63] - s_cum[tid]);
        g_el[(size_t)blk * 64 + tid] = __expf(s_cum[tid]);
    }
    if (tid == 0) g_T[blk] = __expf(s_cum[63]);
    __syncthreads();

    const int er = lane >> 2, ec = (lane & 3) << 1;

    // ---- step A: G = C @ B^T, mask/decay -> M ----
    {
        float acc[4][4];
#pragma unroll
        for (int g = 0; g < 4; g++)
#pragma unroll
            for (int e = 0; e < 4; e++) acc[g][e] = 0.f;
#pragma unroll
        for (int k16 = 0; k16 < 4; k16++) {
            uint32_t ah[4], al[4];
            uint32_t aoff = swz128(r0 + (lane & 15),
                                   k16 * 32 + ((lane >> 4) << 4));
            ldsm_x4(ah[0], ah[1], ah[2], ah[3], sb + OFF_CH + aoff);
            ldsm_x4(al[0], al[1], al[2], al[3], sb + OFF_CL + aoff);
            uint32_t bhf[2][4], blf[2][4];
#pragma unroll
            for (int g2 = 0; g2 < 2; g2++) {
                uint32_t boff =
                    swz128(c0 + g2 * 16 + (lane & 7) + ((lane >> 4) << 3),
                           k16 * 32 + (((lane >> 3) & 1) << 4));
                ldsm_x4(bhf[g2][0], bhf[g2][1], bhf[g2][2], bhf[g2][3],
                        sb + OFF_BH + boff);
                ldsm_x4(blf[g2][0], blf[g2][1], blf[g2][2], blf[g2][3],
                        sb + OFF_BL + boff);
            }
#pragma unroll
            for (int g = 0; g < 4; g++)
                mma3(acc[g], ah, al, &bhf[g >> 1][(g & 1) << 1],
                     &blf[g >> 1][(g & 1) << 1]);
        }
#pragma unroll
        for (int g = 0; g < 4; g++) {
            int s0 = c0 + g * 8 + ec;
            float cs0 = s_cum[s0], cs1 = s_cum[s0 + 1];
            float d0 = s_dt[s0], d1 = s_dt[s0 + 1];
#pragma unroll
            for (int hf = 0; hf < 2; hf++) {
                int l = r0 + er + hf * 8;
                float cl = s_cum[l];
                float v0 = (s0     <= l) ? acc[g][hf * 2 + 0] * __expf(cl - cs0) * d0 : 0.f;
                float v1 = (s0 + 1 <= l) ? acc[g][hf * 2 + 1] * __expf(cl - cs1) * d1 : 0.f;
                uint32_t wh, wl;
                split2(v0, v1, wh, wl);
                uint32_t so = swz128(l, s0 * 2);
                *(uint32_t*)(sm + OFF_MH + so) = wh;
                *(uint32_t*)(sm + OFF_ML + so) = wl;
            }
        }
    }
    __syncthreads();

    // ---- CX = coef(l) * x ----
#pragma unroll
    for (int i = 0; i < 8; i++) {
        int flat = tid + (i << 8);
        int l = flat >> 5, q2 = flat & 31;
        uint32_t so = swz128(l, q2 * 4);
        float2 v = unpack2(*(uint32_t*)(sm + OFF_XH + so),
                           *(uint32_t*)(sm + OFF_XL + so));
        float cf = s_coef[l];
        uint32_t oh, ol;
        split2(v.x * cf, v.y * cf, oh, ol);
        *(uint32_t*)(sm + OFF_CH + so) = oh;
        *(uint32_t*)(sm + OFF_CL + so) = ol;
    }

    // ---- step B: Y = M @ x (+ D skip) ----
    {
        float acc[4][4];
#pragma unroll
        for (int g = 0; g < 4; g++)
#pragma unroll
            for (int e = 0; e < 4; e++) acc[g][e] = 0.f;
#pragma unroll
        for (int k16 = 0; k16 < 4; k16++) {
            uint32_t ah[4], al[4];
            uint32_t aoff = swz128(r0 + (lane & 15),
                                   k16 * 32 + ((lane >> 4) << 4));
            ldsm_x4(ah[0], ah[1], ah[2], ah[3], sb + OFF_MH + aoff);
            ldsm_x4(al[0], al[1], al[2], al[3], sb + OFF_ML + aoff);
            uint32_t bhf[2][4], blf[2][4];
#pragma unroll
            for (int g2 = 0; g2 < 2; g2++) {
                uint32_t boff =
                    swz128(k16 * 16 + ((lane >> 3) & 1) * 8 + (lane & 7),
                           (c0 + g2 * 16) * 2 + (((lane >> 4) & 1) << 4));
                ldsm_x4_t(bhf[g2][0], bhf[g2][1], bhf[g2][2], bhf[g2][3],
                          sb + OFF_XH + boff);
                ldsm_x4_t(blf[g2][0], blf[g2][1], blf[g2][2], blf[g2][3],
                          sb + OFF_XL + boff);
            }
#pragma unroll
            for (int g = 0; g < 4; g++)
                mma3(acc[g], ah, al, &bhf[g >> 1][(g & 1) << 1],
                     &blf[g >> 1][(g & 1) << 1]);
        }
#pragma unroll
        for (int g = 0; g < 4; g++) {
            int p0 = c0 + g * 8 + ec;
#pragma unroll
            for (int hf = 0; hf < 2; hf++) {
                int l = r0 + er + hf * 8;
                uint32_t so = swz128(l, p0 * 2);
                float2 xv = unpack2(*(uint32_t*)(sm + OFF_XH + so),
                                    *(uint32_t*)(sm + OFF_XL + so));
                *(float2*)&g_y[(size_t)(m0 + l) * D_INNER + h * HEADDIM + p0] =
                    make_float2(acc[g][hf * 2 + 0] + Dh * xv.x,
                                acc[g][hf * 2 + 1] + Dh * xv.y);
            }
        }
    }
    __syncthreads();

    // ---- step C: S(p,n) = CX^T @ B ----
    {
        float acc[4][4];
#pragma unroll
        for (int g = 0; g < 4; g++)
#pragma unroll
            for (int e = 0; e < 4; e++) acc[g][e] = 0.f;
#pragma unroll
        for (int k16 = 0; k16 < 4; k16++) {
            uint32_t ah[4], al[4];
            uint32_t aoff =
                swz128(k16 * 16 + ((lane >> 4) & 1) * 8 + (lane & 7),
                       r0 * 2 + (((lane >> 3) & 1) << 4));
            ldsm_x4_t(ah[0], ah[1], ah[2], ah[3], sb + OFF_CH + aoff);
            ldsm_x4_t(al[0], al[1], al[2], al[3], sb + OFF_CL + aoff);
            uint32_t bhf[2][4], blf[2][4];
#pragma unroll
            for (int g2 = 0; g2 < 2; g2++) {
                uint32_t boff =
                    swz128(k16 * 16 + ((lane >> 3) & 1) * 8 + (lane & 7),
                           (c0 + g2 * 16) * 2 + (((lane >> 4) & 1) << 4));
                ldsm_x4_t(bhf[g2][0], bhf[g2][1], bhf[g2][2], bhf[g2][3],
                          sb + OFF_BH + boff);
                ldsm_x4_t(blf[g2][0], blf[g2][1], blf[g2][2], blf[g2][3],
                          sb + OFF_BL + boff);
            }
#pragma unroll
            for (int g = 0; g < 4; g++)
                mma3(acc[g], ah, al, &bhf[g >> 1][(g & 1) << 1],
                     &blf[g >> 1][(g & 1) << 1]);
        }
        const size_t sbase = (size_t)blk * 4096;
#pragma unroll
        for (int g = 0; g < 4; g++) {
            int n0 = c0 + g * 8 + ec;
#pragma unroll
            for (int hf = 0; hf < 2; hf++) {
                int p = r0 + er + hf * 8;
                *(float2*)&g_cs[sbase + p * 64 + n0] =
                    make_float2(acc[g][hf * 2 + 0], acc[g][hf * 2 + 1]);
            }
        }
    }
}

// ------------------------- SSD phase 2: inter-chunk scan (16x parallel) -----
__global__ void __launch_bounds__(256) ssd_phase2() {
    const int slice = blockIdx.x & 15;
    const int bh    = blockIdx.x >> 4;
    const int off   = slice * 256 + threadIdx.x;
    float st = 0.f;
    const size_t b0 = (size_t)bh * NCHUNK * 4096;
    const float* Tp = &g_T[bh * NCHUNK];
#pragma unroll 4
    for (int c = 0; c < NCHUNK; c++) {
        const size_t base = b0 + (size_t)c * 4096 + off;
        g_ps[base] = st;
        st = st * Tp[c] + g_cs[base];
    }
}

// ------------------------- SSD phase 3 (tensor cores) -----------------------
__global__ void __launch_bounds__(256) ssd3_tc() {
    __shared__ char t_Ch[8192], t_Cl[8192], t_Sh[8192], t_Sl[8192];
    __shared__ float s_el[64];
    const uint32_t aCh = smem_u32(t_Ch), aCl = smem_u32(t_Cl);
    const uint32_t aSh = smem_u32(t_Sh), aSl = smem_u32(t_Sl);

    const int blk = blockIdx.x;
    const int c   = blk & (NCHUNK - 1);
    const int bh  = blk >> 6;
    const int b = bh >> 5, h = bh & 31;
    const int tid = threadIdx.x, wid = tid >> 5, lane = tid & 31;
    const int r0 = (wid & 3) * 16, c0 = (wid >> 2) * 32;
    const int m0 = b * T_LEN + c * CHUNK;

#pragma unroll
    for (int i = 0; i < 8; i++) {
        int flat = tid + (i << 8);
        int l = flat >> 5, q2 = flat & 31;
        uint32_t so = swz128(l, q2 * 4);
        float2 vc = *(const float2*)&g_xbc[(size_t)(m0 + l) * CONV_DIM +
                                           D_INNER + D_STATE + q2 * 2];
        uint32_t wh, wl;
        split2(vc.x, vc.y, wh, wl);
        *(uint32_t*)(t_Ch + so) = wh;
        *(uint32_t*)(t_Cl + so) = wl;
        float2 vs = *(const float2*)&g_ps[(size_t)blk * 4096 + l * 64 + q2 * 2];
        split2(vs.x, vs.y, wh, wl);
        *(uint32_t*)(t_Sh + so) = wh;
        *(uint32_t*)(t_Sl + so) = wl;
    }
    if (tid < 64) s_el[tid] = g_el[(size_t)blk * 64 + tid];
    __syncthreads();

    float acc[4][4];
#pragma unroll
    for (int g = 0; g < 4; g++)
#pragma unroll
        for (int e = 0; e < 4; e++) acc[g][e] = 0.f;
#pragma unroll
    for (int k16 = 0; k16 < 4; k16++) {
        uint32_t ah[4], al[4];
        uint32_t aoff = swz128(r0 + (lane & 15), k16 * 32 + ((lane >> 4) << 4));
        ldsm_x4(ah[0], ah[1], ah[2], ah[3], aCh + aoff);
        ldsm_x4(al[0], al[1], al[2], al[3], aCl + aoff);
        uint32_t bhf[2][4], blf[2][4];
#pragma unroll
        for (int g2 = 0; g2 < 2; g2++) {
            uint32_t boff =
                swz128(c0 + g2 * 16 + (lane & 7) + ((lane >> 4) << 3),
                       k16 * 32 + (((lane >> 3) & 1) << 4));
            ldsm_x4(bhf[g2][0], bhf[g2][1], bhf[g2][2], bhf[g2][3], aSh + boff);
            ldsm_x4(blf[g2][0], blf[g2][1], blf[g2][2], blf[g2][3], aSl + boff);
        }
#pragma unroll
        for (int g = 0; g < 4; g++)
            mma3(acc[g], ah, al, &bhf[g >> 1][(g & 1) << 1],
                 &blf[g >> 1][(g & 1) << 1]);
    }
    const int er = lane >> 2, ec = (lane & 3) << 1;
#pragma unroll
    for (int g = 0; g < 4; g++) {
        int p0 = c0 + g * 8 + ec;
#pragma unroll
        for (int hf = 0; hf < 2; hf++) {
            int l = r0 + er + hf * 8;
            float el = s_el[l];
            float2* yp =
                (float2*)&g_y[(size_t)(m0 + l) * D_INNER + h * HEADDIM + p0];
            float2 cur = *yp;
            cur.x += el * acc[g][hf * 2 + 0];
            cur.y += el * acc[g][hf * 2 + 1];
            *yp = cur;
        }
    }
}

// ------------------------- gate + RMSNorm -> fp16 ---------------------------
__global__ void gate_rms_kernel(const float* __restrict__ norm_w,
                                __half* __restrict__ yh) {
    const int m = blockIdx.x;
    const int tid = threadIdx.x;
    const size_t ybase = (size_t)m * D_INNER;
    const size_t zbase = (size_t)m * D_IN_PROJ;
    float vals[8];
    float ssum = 0.f;
#pragma unroll
    for (int i = 0; i < 8; i++) {
        const int idx = tid + i * 256;
        const float yv = g_y[ybase + idx];
        const float z = g_zxbcdt[zbase + idx];
        const float g = yv * z / (1.f + expf(-z));
        vals[i] = g;
        ssum += g * g;
    }
    __shared__ float red[256];
    red[tid] = ssum;
    __syncthreads();
    for (int s = 128; s > 0; s >>= 1) {
        if (tid < s) red[tid] += red[tid + s];
        __syncthreads();
    }
    const float scale = rsqrtf(red[0] / (float)D_INNER + 1e-5f);
#pragma unroll
    for (int i = 0; i < 8; i++) {
        const int idx = tid + i * 256;
        yh[ybase + idx] = __float2half_rn(vals[i] * scale * norm_w[idx]);
    }
}

// ---------------------------------------------------------------------------
extern "C" void kernel_launch(void* const* d_in, const int* in_sizes, int n_in,
                              void* d_out, int out_size) {
    const float* u       = (const float*)d_in[0];
    const float* W_in    = (const float*)d_in[1];
    const float* conv_w  = (const float*)d_in[2];
    const float* conv_b  = (const float*)d_in[3];
    const float* dt_bias = (const float*)d_in[4];
    const float* A_log   = (const float*)d_in[5];
    const float* Dv      = (const float*)d_in[6];
    const float* norm_w  = (const float*)d_in[7];
    const float* W_out   = (const float*)d_in[8];
    float* out = (float*)d_out;

    float* zx_p;
    __half *uh, *wih, *yh, *woh;
    cudaGetSymbolAddress((void**)&zx_p, g_zxbcdt);
    cudaGetSymbolAddress((void**)&uh, g_uh);
    cudaGetSymbolAddress((void**)&wih, g_wih);
    cudaGetSymbolAddress((void**)&yh, g_yh);
    cudaGetSymbolAddress((void**)&woh, g_woh);

    cudaFuncSetAttribute(gemm_mma_kernel,
                         cudaFuncAttributeMaxDynamicSharedMemorySize, GEMM_SMEM);
    cudaFuncSetAttribute(ssd1_tc,
                         cudaFuncAttributeMaxDynamicSharedMemorySize, SSD1_SMEM);

    {
        int n = M_TOK * D_MODEL;
        cvt_kernel<<<(n / 2 + 255) / 256, 256>>>(u, uh, n);
        n = D_IN_PROJ * D_MODEL;
        cvt_kernel<<<(n / 2 + 255) / 256, 256>>>(W_in, wih, n);
    }

    gemm_mma_kernel<<<dim3((D_IN_PROJ + 127) / 128, M_TOK / 128), 256,
                      GEMM_SMEM>>>(uh, wih, zx_p, M_TOK, D_IN_PROJ, D_MODEL);

    dt_kernel<<<(M_TOK * NHEADS) / 256, 256>>>(dt_bias);
    conv_silu_kernel<<<dim3(CONV_DIM / 128, M_TOK / 64), 256>>>(conv_w, conv_b);

    ssd1_tc<<<NBH * NCHUNK, 256, SSD1_SMEM>>>(A_log, Dv);
    ssd_phase2<<<NBH * 16, 256>>>();
    ssd3_tc<<<NBH * NCHUNK, 256>>>();

    gate_rms_kernel<<<M_TOK, 256>>>(norm_w, yh);

    {
        int n = D_MODEL * D_INNER;
        cvt_kernel<<<(n / 2 + 255) / 256, 256>>>(W_out, woh, n);
    }

    gemm_mma_kernel<<<dim3(D_MODEL / 128, M_TOK / 128), 256,
                      GEMM_SMEM>>>(yh, woh, out, M_TOK, D_MODEL, D_INNER);
}

// round 7
// speedup vs baseline: 9.4215x; 1.0902x over previous
#include <cuda_runtime.h>
#include <cuda_bf16.h>
#include <cuda_fp16.h>
#include <math.h>
#include <stdint.h>

#define D_MODEL   1024
#define D_STATE   64
#define D_CONV    4
#define D_INNER   2048
#define NHEADS    32
#define HEADDIM   64
#define CHUNK     64
#define CONV_DIM  2176
#define D_IN_PROJ 4256
#define B_SZ      2
#define T_LEN     4096
#define M_TOK     (B_SZ * T_LEN)   // 8192
#define NCHUNK    (T_LEN / CHUNK)  // 64
#define NBH       (B_SZ * NHEADS)  // 64

// ------------------------- scratch (device globals) -------------------------
__device__ float g_zxbcdt[(size_t)M_TOK * D_IN_PROJ];
__device__ __half g_xbc[(size_t)M_TOK * CONV_DIM];     // fp16 post conv+silu
__device__ float g_dt[(size_t)M_TOK * NHEADS];
__device__ float g_y[(size_t)M_TOK * D_INNER];

__device__ __half g_uh[(size_t)M_TOK * D_MODEL];
__device__ __half g_wih[(size_t)D_IN_PROJ * D_MODEL];
__device__ __half g_yh[(size_t)M_TOK * D_INNER];
__device__ __half g_woh[(size_t)D_MODEL * D_INNER];

__device__ float g_cs[(size_t)NBH * NCHUNK * 64 * 64];
__device__ float g_ps[(size_t)NBH * NCHUNK * 64 * 64];
__device__ float g_T[NBH * NCHUNK];
__device__ float g_el[(size_t)NBH * NCHUNK * CHUNK];

// ------------------------- helpers ------------------------------------------
__device__ __forceinline__ uint32_t smem_u32(const void* p) {
    uint32_t a;
    asm("{ .reg .u64 t; cvta.to.shared.u64 t, %1; cvt.u32.u64 %0, t; }"
        : "=r"(a) : "l"(p));
    return a;
}
__device__ __forceinline__ void ldsm_x4(uint32_t& r0, uint32_t& r1,
                                        uint32_t& r2, uint32_t& r3,
                                        uint32_t addr) {
    asm volatile("ldmatrix.sync.aligned.m8n8.x4.shared.b16 {%0,%1,%2,%3}, [%4];"
                 : "=r"(r0), "=r"(r1), "=r"(r2), "=r"(r3) : "r"(addr));
}
__device__ __forceinline__ void ldsm_x4_t(uint32_t& r0, uint32_t& r1,
                                          uint32_t& r2, uint32_t& r3,
                                          uint32_t addr) {
    asm volatile("ldmatrix.sync.aligned.m8n8.x4.trans.shared.b16 {%0,%1,%2,%3}, [%4];"
                 : "=r"(r0), "=r"(r1), "=r"(r2), "=r"(r3) : "r"(addr));
}
__device__ __forceinline__ void mma_fp16(float* c, const uint32_t* a,
                                         uint32_t b0, uint32_t b1) {
    asm volatile(
        "mma.sync.aligned.m16n8k16.row.col.f32.f16.f16.f32 "
        "{%0,%1,%2,%3}, {%4,%5,%6,%7}, {%8,%9}, {%0,%1,%2,%3};"
        : "+f"(c[0]), "+f"(c[1]), "+f"(c[2]), "+f"(c[3])
        : "r"(a[0]), "r"(a[1]), "r"(a[2]), "r"(a[3]), "r"(b0), "r"(b1));
}
__device__ __forceinline__ void cp16(uint32_t dst, const void* src) {
    asm volatile("cp.async.cg.shared.global [%0], [%1], 16;"
                 :: "r"(dst), "l"(src));
}
__device__ __forceinline__ void cp16z(uint32_t dst, const void* src, int valid) {
    int sz = valid ? 16 : 0;
    asm volatile("cp.async.cg.shared.global [%0], [%1], 16, %2;"
                 :: "r"(dst), "l"(src), "r"(sz));
}
#define CP_COMMIT() asm volatile("cp.async.commit_group;" ::: "memory")
#define CP_WAIT(N)  asm volatile("cp.async.wait_group %0;" :: "n"(N) : "memory")

// GEMM smem tile: [128 rows][32 halves] = 64B/row, XOR-swizzled 16B chunks.
__device__ __forceinline__ uint32_t swz(int row, int kb) {
    return (uint32_t)(row * 64 + ((((kb >> 4) ^ (row & 3)) << 4) | (kb & 15)));
}
// SSD smem tile: [64 rows][64 halves] = 128B/row, XOR-swizzled.
__device__ __forceinline__ uint32_t swz128(int row, int cb) {
    return (uint32_t)(row * 128 + (cb ^ ((row & 7) << 4)));
}
__device__ __forceinline__ uint32_t packh2(float a, float b) {
    __half2 h; h.x = __float2half_rn(a); h.y = __float2half_rn(b);
    return *(uint32_t*)&h;
}
__device__ __forceinline__ float2 unpackh2(uint32_t w) {
    __half2 h = *(__half2*)&w;
    return make_float2(__half2float(h.x), __half2float(h.y));
}

// ------------------------- fp32 -> fp16 convert -----------------------------
__global__ void cvt_kernel(const float* __restrict__ src,
                           __half* __restrict__ dst, int n) {
    int i = blockIdx.x * 256 + threadIdx.x;
    if (i * 2 < n) {
        float2 v = *(const float2*)(src + i * 2);
        *(__half2*)(dst + i * 2) = __floats2half2_rn(v.x, v.y);
    }
}

// ------------------------- HMMA GEMM (fp16): C = A @ B^T --------------------
#define TILE_B   8192
#define STAGE_B  (2 * TILE_B)
#define NSTAGE   4
#define GEMM_SMEM (NSTAGE * STAGE_B)   // 64 KB
__global__ void __launch_bounds__(256) gemm_mma_kernel(
    const __half* __restrict__ A, const __half* __restrict__ B,
    float* __restrict__ C, int M, int N, int K) {
    extern __shared__ char smem[];
    const uint32_t sb = smem_u32(smem);

    const int tid  = threadIdx.x;
    const int wid  = tid >> 5;
    const int lane = tid & 31;
    const int m0 = blockIdx.y << 7;
    const int n0 = blockIdx.x << 7;
    const int wm0 = (wid >> 2) << 6;
    const int wn0 = (wid & 3) << 5;

    const int r0c = tid >> 2, c0c = tid & 3;
    const int r1c = (tid + 256) >> 2, c1c = tid & 3;

    float acc[4][4][4];
#pragma unroll
    for (int f = 0; f < 4; f++)
#pragma unroll
        for (int g = 0; g < 4; g++)
#pragma unroll
            for (int e = 0; e < 4; e++) acc[f][g][e] = 0.f;

    const int nk = K >> 5;

    auto load_stage = [&](int kc, int s) {
        const int k0 = kc << 5;
        const uint32_t st = sb + s * STAGE_B;
        {
            const size_t o0 = (size_t)(m0 + r0c) * K + k0 + c0c * 8;
            const size_t o1 = (size_t)(m0 + r1c) * K + k0 + c1c * 8;
            cp16(st + swz(r0c, c0c * 16), A + o0);
            cp16(st + swz(r1c, c1c * 16), A + o1);
        }
        {
            const int v0 = (n0 + r0c) < N, v1 = (n0 + r1c) < N;
            const size_t o0 = v0 ? (size_t)(n0 + r0c) * K + k0 + c0c * 8 : 0;
            const size_t o1 = v1 ? (size_t)(n0 + r1c) * K + k0 + c1c * 8 : 0;
            cp16z(st + TILE_B + swz(r0c, c0c * 16), B + o0, v0);
            cp16z(st + TILE_B + swz(r1c, c1c * 16), B + o1, v1);
        }
        CP_COMMIT();
    };

    load_stage(0, 0);
    load_stage(1, 1);
    load_stage(2, 2);

    const int a_row = lane & 15;
    const int a_kb  = (lane >> 4) << 4;
    const int b_row = (lane & 7) + ((lane >> 4) << 3);
    const int b_kb  = ((lane >> 3) & 1) << 4;

    for (int kc = 0; kc < nk; kc++) {
        CP_WAIT(2);
        __syncthreads();
        if (kc + 3 < nk) load_stage(kc + 3, (kc + 3) & 3);
        else CP_COMMIT();

        const uint32_t st = sb + (kc & 3) * STAGE_B;
        const uint32_t sA = st, sB = st + TILE_B;

#pragma unroll
        for (int kk = 0; kk < 2; kk++) {
            const int kb_a = kk * 32 + a_kb;
            const int kb_b = kk * 32 + b_kb;
            uint32_t ah[4][4], bh[2][4];
#pragma unroll
            for (int f = 0; f < 4; f++) {
                const int row = wm0 + f * 16 + a_row;
                ldsm_x4(ah[f][0], ah[f][1], ah[f][2], ah[f][3],
                        sA + swz(row, kb_a));
            }
#pragma unroll
            for (int g2 = 0; g2 < 2; g2++) {
                const int row = wn0 + g2 * 16 + b_row;
                ldsm_x4(bh[g2][0], bh[g2][1], bh[g2][2], bh[g2][3],
                        sB + swz(row, kb_b));
            }
#pragma unroll
            for (int f = 0; f < 4; f++)
#pragma unroll
                for (int g = 0; g < 4; g++) {
                    const uint32_t* bf = &bh[g >> 1][(g & 1) << 1];
                    mma_fp16(acc[f][g], ah[f], bf[0], bf[1]);
                }
        }
    }

    const int er = lane >> 2;
    const int ec = (lane & 3) << 1;
#pragma unroll
    for (int f = 0; f < 4; f++) {
        const int row = m0 + wm0 + f * 16 + er;
#pragma unroll
        for (int g = 0; g < 4; g++) {
            const int col = n0 + wn0 + g * 8 + ec;
            if (col < N) {
                *(float2*)&C[(size_t)row * N + col] =
                    make_float2(acc[f][g][0], acc[f][g][1]);
                *(float2*)&C[(size_t)(row + 8) * N + col] =
                    make_float2(acc[f][g][2], acc[f][g][3]);
            }
        }
    }
}

// ------------------------- dt = softplus(raw + bias) ------------------------
__global__ void dt_kernel(const float* __restrict__ dt_bias) {
    const int idx = blockIdx.x * 256 + threadIdx.x;
    const int m = idx >> 5;
    const int h = idx & 31;
    float v = g_zxbcdt[(size_t)m * D_IN_PROJ + (D_INNER + CONV_DIM) + h] + dt_bias[h];
    g_dt[idx] = (v > 20.f) ? v : log1pf(expf(v));
}

// ------------------------- tiled depthwise conv + SiLU -> fp16 --------------
__global__ void __launch_bounds__(256) conv_silu_kernel(
    const float* __restrict__ w, const float* __restrict__ bias) {
    __shared__ float sx[67][128];
    const int cb = blockIdx.x;
    const int tb = blockIdx.y;
    const int tid = threadIdx.x;
    const int m0 = tb * 64;
    const int zero_head = ((m0 & (T_LEN - 1)) == 0);

    for (int idx = tid; idx < 67 * 128; idx += 256) {
        const int r = idx >> 7, ch = idx & 127;
        float v = 0.f;
        if (r >= 3 || !zero_head)
            v = g_zxbcdt[(size_t)(m0 - 3 + r) * D_IN_PROJ + D_INNER +
                         cb * 128 + ch];
        sx[r][ch] = v;
    }
    __syncthreads();

    const int ch = tid & 127;
    const int th = (tid >> 7) * 32;
    const int gc = cb * 128 + ch;
    const float w0 = w[gc * 4 + 0], w1 = w[gc * 4 + 1];
    const float w2 = w[gc * 4 + 2], w3 = w[gc * 4 + 3];
    const float bz = bias[gc];
#pragma unroll 8
    for (int i = 0; i < 32; i++) {
        const int t = th + i;
        float acc = bz + w0 * sx[t][ch] + w1 * sx[t + 1][ch] +
                    w2 * sx[t + 2][ch] + w3 * sx[t + 3][ch];
        g_xbc[(size_t)(m0 + t) * CONV_DIM + gc] =
            __float2half_rn(acc / (1.f + expf(-acc)));
    }
}

// ------------------------- SSD phase 1 (fp16 tensor cores) ------------------
#define OFF_X 0
#define OFF_B 8192
#define OFF_C 16384
#define OFF_M 24576
__global__ void __launch_bounds__(256) ssd1_tc(const float* __restrict__ A_log,
                                               const float* __restrict__ Dvec) {
    __shared__ __align__(16) char sm[32768];
    __shared__ float s_cum[64], s_dt[64], s_coef[64];
    const uint32_t sb = smem_u32(sm);

    const int blk = blockIdx.x;
    const int c   = blk & (NCHUNK - 1);
    const int bh  = blk >> 6;
    const int b = bh >> 5, h = bh & 31;
    const int tid = threadIdx.x, wid = tid >> 5, lane = tid & 31;
    const int r0 = (wid & 3) * 16, c0 = (wid >> 2) * 32;
    const int m0 = b * T_LEN + c * CHUNK;
    const float Ahc = -expf(A_log[h]);
    const float Dh  = Dvec[h];

    // cp.async x/B/C fp16 tiles into swizzled smem (1536 16B chunks)
#pragma unroll
    for (int i = 0; i < 6; i++) {
        int flat = tid + (i << 8);
        int t3 = flat >> 9;
        int wt = flat & 511;
        int l = wt >> 3, j = wt & 7;
        int off = (t3 == 0) ? h * HEADDIM : (t3 == 1) ? D_INNER
                                                      : D_INNER + D_STATE;
        cp16(sb + t3 * 8192 + swz128(l, j * 16),
             g_xbc + (size_t)(m0 + l) * CONV_DIM + off + j * 8);
    }
    CP_COMMIT();
    if (tid < 64) s_dt[tid] = g_dt[(size_t)(m0 + tid) * NHEADS + h];
    CP_WAIT(0);
    __syncthreads();
    if (wid == 0) {
        float v0 = Ahc * s_dt[lane * 2], v1 = Ahc * s_dt[lane * 2 + 1];
        float s = v0 + v1;
#pragma unroll
        for (int o = 1; o < 32; o <<= 1) {
            float t = __shfl_up_sync(0xFFFFFFFF, s, o);
            if (lane >= o) s += t;
        }
        float excl = s - (v0 + v1);
        s_cum[lane * 2] = excl + v0;
        s_cum[lane * 2 + 1] = excl + v0 + v1;
    }
    __syncthreads();
    if (tid < 64) {
        s_coef[tid] = s_dt[tid] * __expf(s_cum[63] - s_cum[tid]);
        g_el[(size_t)blk * 64 + tid] = __expf(s_cum[tid]);
    }
    if (tid == 0) g_T[blk] = __expf(s_cum[63]);
    __syncthreads();

    const int er = lane >> 2, ec = (lane & 3) << 1;

    // ---- step A: G = C @ B^T, mask/decay -> M (fp16) ----
    {
        float acc[4][4];
#pragma unroll
        for (int g = 0; g < 4; g++)
#pragma unroll
            for (int e = 0; e < 4; e++) acc[g][e] = 0.f;
#pragma unroll
        for (int k16 = 0; k16 < 4; k16++) {
            uint32_t ah[4];
            uint32_t aoff = swz128(r0 + (lane & 15),
                                   k16 * 32 + ((lane >> 4) << 4));
            ldsm_x4(ah[0], ah[1], ah[2], ah[3], sb + OFF_C + aoff);
            uint32_t bhf[2][4];
#pragma unroll
            for (int g2 = 0; g2 < 2; g2++) {
                uint32_t boff =
                    swz128(c0 + g2 * 16 + (lane & 7) + ((lane >> 4) << 3),
                           k16 * 32 + (((lane >> 3) & 1) << 4));
                ldsm_x4(bhf[g2][0], bhf[g2][1], bhf[g2][2], bhf[g2][3],
                        sb + OFF_B + boff);
            }
#pragma unroll
            for (int g = 0; g < 4; g++) {
                const uint32_t* bf = &bhf[g >> 1][(g & 1) << 1];
                mma_fp16(acc[g], ah, bf[0], bf[1]);
            }
        }
#pragma unroll
        for (int g = 0; g < 4; g++) {
            int s0 = c0 + g * 8 + ec;
            float cs0 = s_cum[s0], cs1 = s_cum[s0 + 1];
            float d0 = s_dt[s0], d1 = s_dt[s0 + 1];
#pragma unroll
            for (int hf = 0; hf < 2; hf++) {
                int l = r0 + er + hf * 8;
                float cl = s_cum[l];
                float v0 = (s0     <= l) ? acc[g][hf * 2 + 0] * __expf(cl - cs0) * d0 : 0.f;
                float v1 = (s0 + 1 <= l) ? acc[g][hf * 2 + 1] * __expf(cl - cs1) * d1 : 0.f;
                *(uint32_t*)(sm + OFF_M + swz128(l, s0 * 2)) = packh2(v0, v1);
            }
        }
    }
    __syncthreads();

    // ---- CX = coef(l) * x (overwrites C tile) ----
#pragma unroll
    for (int i = 0; i < 8; i++) {
        int flat = tid + (i << 8);
        int l = flat >> 5, q2 = flat & 31;
        uint32_t so = swz128(l, q2 * 4);
        float2 v = unpackh2(*(uint32_t*)(sm + OFF_X + so));
        float cf = s_coef[l];
        *(uint32_t*)(sm + OFF_C + so) = packh2(v.x * cf, v.y * cf);
    }

    // ---- step B: Y = M @ x (+ D skip) ----
    {
        float acc[4][4];
#pragma unroll
        for (int g = 0; g < 4; g++)
#pragma unroll
            for (int e = 0; e < 4; e++) acc[g][e] = 0.f;
#pragma unroll
        for (int k16 = 0; k16 < 4; k16++) {
            uint32_t ah[4];
            uint32_t aoff = swz128(r0 + (lane & 15),
                                   k16 * 32 + ((lane >> 4) << 4));
            ldsm_x4(ah[0], ah[1], ah[2], ah[3], sb + OFF_M + aoff);
            uint32_t bhf[2][4];
#pragma unroll
            for (int g2 = 0; g2 < 2; g2++) {
                uint32_t boff =
                    swz128(k16 * 16 + ((lane >> 3) & 1) * 8 + (lane & 7),
                           (c0 + g2 * 16) * 2 + (((lane >> 4) & 1) << 4));
                ldsm_x4_t(bhf[g2][0], bhf[g2][1], bhf[g2][2], bhf[g2][3],
                          sb + OFF_X + boff);
            }
#pragma unroll
            for (int g = 0; g < 4; g++) {
                const uint32_t* bf = &bhf[g >> 1][(g & 1) << 1];
                mma_fp16(acc[g], ah, bf[0], bf[1]);
            }
        }
#pragma unroll
        for (int g = 0; g < 4; g++) {
            int p0 = c0 + g * 8 + ec;
#pragma unroll
            for (int hf = 0; hf < 2; hf++) {
                int l = r0 + er + hf * 8;
                float2 xv = unpackh2(*(uint32_t*)(sm + OFF_X + swz128(l, p0 * 2)));
                *(float2*)&g_y[(size_t)(m0 + l) * D_INNER + h * HEADDIM + p0] =
                    make_float2(acc[g][hf * 2 + 0] + Dh * xv.x,
                                acc[g][hf * 2 + 1] + Dh * xv.y);
            }
        }
    }
    __syncthreads();

    // ---- step C: S(p,n) = CX^T @ B ----
    {
        float acc[4][4];
#pragma unroll
        for (int g = 0; g < 4; g++)
#pragma unroll
            for (int e = 0; e < 4; e++) acc[g][e] = 0.f;
#pragma unroll
        for (int k16 = 0; k16 < 4; k16++) {
            uint32_t ah[4];
            uint32_t aoff =
                swz128(k16 * 16 + ((lane >> 4) & 1) * 8 + (lane & 7),
                       r0 * 2 + (((lane >> 3) & 1) << 4));
            ldsm_x4_t(ah[0], ah[1], ah[2], ah[3], sb + OFF_C + aoff);
            uint32_t bhf[2][4];
#pragma unroll
            for (int g2 = 0; g2 < 2; g2++) {
                uint32_t boff =
                    swz128(k16 * 16 + ((lane >> 3) & 1) * 8 + (lane & 7),
                           (c0 + g2 * 16) * 2 + (((lane >> 4) & 1) << 4));
                ldsm_x4_t(bhf[g2][0], bhf[g2][1], bhf[g2][2], bhf[g2][3],
                          sb + OFF_B + boff);
            }
#pragma unroll
            for (int g = 0; g < 4; g++) {
                const uint32_t* bf = &bhf[g >> 1][(g & 1) << 1];
                mma_fp16(acc[g], ah, bf[0], bf[1]);
            }
        }
        const size_t sbase = (size_t)blk * 4096;
#pragma unroll
        for (int g = 0; g < 4; g++) {
            int n0 = c0 + g * 8 + ec;
#pragma unroll
            for (int hf = 0; hf < 2; hf++) {
                int p = r0 + er + hf * 8;
                *(float2*)&g_cs[sbase + p * 64 + n0] =
                    make_float2(acc[g][hf * 2 + 0], acc[g][hf * 2 + 1]);
            }
        }
    }
}

// ------------------------- SSD phase 2: inter-chunk scan (16x parallel) -----
__global__ void __launch_bounds__(256) ssd_phase2() {
    const int slice = blockIdx.x & 15;
    const int bh    = blockIdx.x >> 4;
    const int off   = slice * 256 + threadIdx.x;
    float st = 0.f;
    const size_t b0 = (size_t)bh * NCHUNK * 4096;
    const float* Tp = &g_T[bh * NCHUNK];
#pragma unroll 4
    for (int c = 0; c < NCHUNK; c++) {
        const size_t base = b0 + (size_t)c * 4096 + off;
        g_ps[base] = st;
        st = st * Tp[c] + g_cs[base];
    }
}

// ------------------------- SSD phase 3 (fp16 tensor cores) ------------------
__global__ void __launch_bounds__(256) ssd3_tc() {
    __shared__ __align__(16) char t_C[8192];
    __shared__ __align__(16) char t_S[8192];
    __shared__ float s_el[64];
    const uint32_t aC = smem_u32(t_C), aS = smem_u32(t_S);

    const int blk = blockIdx.x;
    const int c   = blk & (NCHUNK - 1);
    const int bh  = blk >> 6;
    const int b = bh >> 5, h = bh & 31;
    const int tid = threadIdx.x, wid = tid >> 5, lane = tid & 31;
    const int r0 = (wid & 3) * 16, c0 = (wid >> 2) * 32;
    const int m0 = b * T_LEN + c * CHUNK;

    // C tile via cp.async (512 chunks)
#pragma unroll
    for (int i = 0; i < 2; i++) {
        int flat = tid + (i << 8);
        int l = flat >> 3, j = flat & 7;
        cp16(aC + swz128(l, j * 16),
             g_xbc + (size_t)(m0 + l) * CONV_DIM + D_INNER + D_STATE + j * 8);
    }
    CP_COMMIT();
    // S tile: fp32 -> fp16 convert
#pragma unroll
    for (int i = 0; i < 8; i++) {
        int flat = tid + (i << 8);
        int l = flat >> 5, q2 = flat & 31;
        float2 vs = *(const float2*)&g_ps[(size_t)blk * 4096 + l * 64 + q2 * 2];
        *(uint32_t*)(t_S + swz128(l, q2 * 4)) = packh2(vs.x, vs.y);
    }
    if (tid < 64) s_el[tid] = g_el[(size_t)blk * 64 + tid];
    CP_WAIT(0);
    __syncthreads();

    float acc[4][4];
#pragma unroll
    for (int g = 0; g < 4; g++)
#pragma unroll
        for (int e = 0; e < 4; e++) acc[g][e] = 0.f;
#pragma unroll
    for (int k16 = 0; k16 < 4; k16++) {
        uint32_t ah[4];
        uint32_t aoff = swz128(r0 + (lane & 15), k16 * 32 + ((lane >> 4) << 4));
        ldsm_x4(ah[0], ah[1], ah[2], ah[3], aC + aoff);
        uint32_t bhf[2][4];
#pragma unroll
        for (int g2 = 0; g2 < 2; g2++) {
            uint32_t boff =
                swz128(c0 + g2 * 16 + (lane & 7) + ((lane >> 4) << 3),
                       k16 * 32 + (((lane >> 3) & 1) << 4));
            ldsm_x4(bhf[g2][0], bhf[g2][1], bhf[g2][2], bhf[g2][3], aS + boff);
        }
#pragma unroll
        for (int g = 0; g < 4; g++) {
            const uint32_t* bf = &bhf[g >> 1][(g & 1) << 1];
            mma_fp16(acc[g], ah, bf[0], bf[1]);
        }
    }
    const int er = lane >> 2, ec = (lane & 3) << 1;
#pragma unroll
    for (int g = 0; g < 4; g++) {
        int p0 = c0 + g * 8 + ec;
#pragma unroll
        for (int hf = 0; hf < 2; hf++) {
            int l = r0 + er + hf * 8;
            float el = s_el[l];
            float2* yp =
                (float2*)&g_y[(size_t)(m0 + l) * D_INNER + h * HEADDIM + p0];
            float2 cur = *yp;
            cur.x += el * acc[g][hf * 2 + 0];
            cur.y += el * acc[g][hf * 2 + 1];
            *yp = cur;
        }
    }
}

// ------------------------- gate + RMSNorm -> fp16 ---------------------------
__global__ void gate_rms_kernel(const float* __restrict__ norm_w,
                                __half* __restrict__ yh) {
    const int m = blockIdx.x;
    const int tid = threadIdx.x;
    const size_t ybase = (size_t)m * D_INNER;
    const size_t zbase = (size_t)m * D_IN_PROJ;
    float vals[8];
    float ssum = 0.f;
#pragma unroll
    for (int i = 0; i < 8; i++) {
        const int idx = tid + i * 256;
        const float yv = g_y[ybase + idx];
        const float z = g_zxbcdt[zbase + idx];
        const float g = yv * z / (1.f + expf(-z));
        vals[i] = g;
        ssum += g * g;
    }
    __shared__ float red[256];
    red[tid] = ssum;
    __syncthreads();
    for (int s = 128; s > 0; s >>= 1) {
        if (tid < s) red[tid] += red[tid + s];
        __syncthreads();
    }
    const float scale = rsqrtf(red[0] / (float)D_INNER + 1e-5f);
#pragma unroll
    for (int i = 0; i < 8; i++) {
        const int idx = tid + i * 256;
        yh[ybase + idx] = __float2half_rn(vals[i] * scale * norm_w[idx]);
    }
}

// ---------------------------------------------------------------------------
extern "C" void kernel_launch(void* const* d_in, const int* in_sizes, int n_in,
                              void* d_out, int out_size) {
    const float* u       = (const float*)d_in[0];
    const float* W_in    = (const float*)d_in[1];
    const float* conv_w  = (const float*)d_in[2];
    const float* conv_b  = (const float*)d_in[3];
    const float* dt_bias = (const float*)d_in[4];
    const float* A_log   = (const float*)d_in[5];
    const float* Dv      = (const float*)d_in[6];
    const float* norm_w  = (const float*)d_in[7];
    const float* W_out   = (const float*)d_in[8];
    float* out = (float*)d_out;

    float* zx_p;
    __half *uh, *wih, *yh, *woh;
    cudaGetSymbolAddress((void**)&zx_p, g_zxbcdt);
    cudaGetSymbolAddress((void**)&uh, g_uh);
    cudaGetSymbolAddress((void**)&wih, g_wih);
    cudaGetSymbolAddress((void**)&yh, g_yh);
    cudaGetSymbolAddress((void**)&woh, g_woh);

    cudaFuncSetAttribute(gemm_mma_kernel,
                         cudaFuncAttributeMaxDynamicSharedMemorySize, GEMM_SMEM);

    {
        int n = M_TOK * D_MODEL;
        cvt_kernel<<<(n / 2 + 255) / 256, 256>>>(u, uh, n);
        n = D_IN_PROJ * D_MODEL;
        cvt_kernel<<<(n / 2 + 255) / 256, 256>>>(W_in, wih, n);
    }

    gemm_mma_kernel<<<dim3((D_IN_PROJ + 127) / 128, M_TOK / 128), 256,
                      GEMM_SMEM>>>(uh, wih, zx_p, M_TOK, D_IN_PROJ, D_MODEL);

    dt_kernel<<<(M_TOK * NHEADS) / 256, 256>>>(dt_bias);
    conv_silu_kernel<<<dim3(CONV_DIM / 128, M_TOK / 64), 256>>>(conv_w, conv_b);

    ssd1_tc<<<NBH * NCHUNK, 256>>>(A_log, Dv);
    ssd_phase2<<<NBH * 16, 256>>>();
    ssd3_tc<<<NBH * NCHUNK, 256>>>();

    gate_rms_kernel<<<M_TOK, 256>>>(norm_w, yh);

    {
        int n = D_MODEL * D_INNER;
        cvt_kernel<<<(n / 2 + 255) / 256, 256>>>(W_out, woh, n);
    }

    gemm_mma_kernel<<<dim3(D_MODEL / 128, M_TOK / 128), 256,
                      GEMM_SMEM>>>(yh, woh, out, M_TOK, D_MODEL, D_INNER);
}

// round 8
// speedup vs baseline: 9.8837x; 1.0491x over previous
#include <cuda_runtime.h>
#include <cuda_bf16.h>
#include <cuda_fp16.h>
#include <math.h>
#include <stdint.h>

#define D_MODEL   1024
#define D_STATE   64
#define D_CONV    4
#define D_INNER   2048
#define NHEADS    32
#define HEADDIM   64
#define CHUNK     64
#define CONV_DIM  2176
#define D_IN_PROJ 4256
#define B_SZ      2
#define T_LEN     4096
#define M_TOK     (B_SZ * T_LEN)   // 8192
#define NCHUNK    (T_LEN / CHUNK)  // 64
#define NBH       (B_SZ * NHEADS)  // 64

// ------------------------- scratch (device globals) -------------------------
__device__ __half g_zxbcdt[(size_t)M_TOK * D_IN_PROJ];  // fp16 GEMM1 output
__device__ __half g_xbc[(size_t)M_TOK * CONV_DIM];      // fp16 post conv+silu
__device__ float  g_dt[(size_t)M_TOK * NHEADS];
__device__ __half g_y[(size_t)M_TOK * D_INNER];         // fp16 SSD output

__device__ __half g_uh[(size_t)M_TOK * D_MODEL];
__device__ __half g_wih[(size_t)D_IN_PROJ * D_MODEL];
__device__ __half g_yh[(size_t)M_TOK * D_INNER];
__device__ __half g_woh[(size_t)D_MODEL * D_INNER];

__device__ __half g_cs[(size_t)NBH * NCHUNK * 64 * 64];  // fp16 chunk states
__device__ __half g_ps[(size_t)NBH * NCHUNK * 64 * 64];  // fp16 prior states
__device__ float  g_T[NBH * NCHUNK];
__device__ float  g_el[(size_t)NBH * NCHUNK * CHUNK];

// ------------------------- helpers ------------------------------------------
__device__ __forceinline__ uint32_t smem_u32(const void* p) {
    uint32_t a;
    asm("{ .reg .u64 t; cvta.to.shared.u64 t, %1; cvt.u32.u64 %0, t; }"
        : "=r"(a) : "l"(p));
    return a;
}
__device__ __forceinline__ void ldsm_x4(uint32_t& r0, uint32_t& r1,
                                        uint32_t& r2, uint32_t& r3,
                                        uint32_t addr) {
    asm volatile("ldmatrix.sync.aligned.m8n8.x4.shared.b16 {%0,%1,%2,%3}, [%4];"
                 : "=r"(r0), "=r"(r1), "=r"(r2), "=r"(r3) : "r"(addr));
}
__device__ __forceinline__ void ldsm_x4_t(uint32_t& r0, uint32_t& r1,
                                          uint32_t& r2, uint32_t& r3,
                                          uint32_t addr) {
    asm volatile("ldmatrix.sync.aligned.m8n8.x4.trans.shared.b16 {%0,%1,%2,%3}, [%4];"
                 : "=r"(r0), "=r"(r1), "=r"(r2), "=r"(r3) : "r"(addr));
}
__device__ __forceinline__ void mma_fp16(float* c, const uint32_t* a,
                                         uint32_t b0, uint32_t b1) {
    asm volatile(
        "mma.sync.aligned.m16n8k16.row.col.f32.f16.f16.f32 "
        "{%0,%1,%2,%3}, {%4,%5,%6,%7}, {%8,%9}, {%0,%1,%2,%3};"
        : "+f"(c[0]), "+f"(c[1]), "+f"(c[2]), "+f"(c[3])
        : "r"(a[0]), "r"(a[1]), "r"(a[2]), "r"(a[3]), "r"(b0), "r"(b1));
}
__device__ __forceinline__ void cp16(uint32_t dst, const void* src) {
    asm volatile("cp.async.cg.shared.global [%0], [%1], 16;"
                 :: "r"(dst), "l"(src));
}
__device__ __forceinline__ void cp16z(uint32_t dst, const void* src, int valid) {
    int sz = valid ? 16 : 0;
    asm volatile("cp.async.cg.shared.global [%0], [%1], 16, %2;"
                 :: "r"(dst), "l"(src), "r"(sz));
}
#define CP_COMMIT() asm volatile("cp.async.commit_group;" ::: "memory")
#define CP_WAIT(N)  asm volatile("cp.async.wait_group %0;" :: "n"(N) : "memory")

__device__ __forceinline__ uint32_t swz(int row, int kb) {
    return (uint32_t)(row * 64 + ((((kb >> 4) ^ (row & 3)) << 4) | (kb & 15)));
}
__device__ __forceinline__ uint32_t swz128(int row, int cb) {
    return (uint32_t)(row * 128 + (cb ^ ((row & 7) << 4)));
}
__device__ __forceinline__ uint32_t packh2(float a, float b) {
    __half2 h = __floats2half2_rn(a, b);
    return *(uint32_t*)&h;
}
__device__ __forceinline__ float2 unpackh2(uint32_t w) {
    __half2 h = *(__half2*)&w;
    return make_float2(__half2float(h.x), __half2float(h.y));
}
__device__ __forceinline__ void store2(float* p, float a, float b) {
    *(float2*)p = make_float2(a, b);
}
__device__ __forceinline__ void store2(__half* p, float a, float b) {
    *(__half2*)p = __floats2half2_rn(a, b);
}

// ------------------------- fp32 -> fp16 convert -----------------------------
__global__ void cvt_kernel(const float* __restrict__ src,
                           __half* __restrict__ dst, int n) {
    int i = blockIdx.x * 256 + threadIdx.x;
    if (i * 2 < n) {
        float2 v = *(const float2*)(src + i * 2);
        *(__half2*)(dst + i * 2) = __floats2half2_rn(v.x, v.y);
    }
}

// ------------------------- HMMA GEMM (fp16): C = A @ B^T --------------------
#define TILE_B   8192
#define STAGE_B  (2 * TILE_B)
#define NSTAGE   4
#define GEMM_SMEM (NSTAGE * STAGE_B)   // 64 KB
template <typename OT>
__global__ void __launch_bounds__(256) gemm_mma_kernel(
    const __half* __restrict__ A, const __half* __restrict__ B,
    OT* __restrict__ C, int M, int N, int K) {
    extern __shared__ char smem[];
    const uint32_t sb = smem_u32(smem);

    const int tid  = threadIdx.x;
    const int wid  = tid >> 5;
    const int lane = tid & 31;
    const int m0 = blockIdx.y << 7;
    const int n0 = blockIdx.x << 7;
    const int wm0 = (wid >> 2) << 6;
    const int wn0 = (wid & 3) << 5;

    const int r0c = tid >> 2, c0c = tid & 3;
    const int r1c = (tid + 256) >> 2, c1c = tid & 3;

    float acc[4][4][4];
#pragma unroll
    for (int f = 0; f < 4; f++)
#pragma unroll
        for (int g = 0; g < 4; g++)
#pragma unroll
            for (int e = 0; e < 4; e++) acc[f][g][e] = 0.f;

    const int nk = K >> 5;

    auto load_stage = [&](int kc, int s) {
        const int k0 = kc << 5;
        const uint32_t st = sb + s * STAGE_B;
        {
            const size_t o0 = (size_t)(m0 + r0c) * K + k0 + c0c * 8;
            const size_t o1 = (size_t)(m0 + r1c) * K + k0 + c1c * 8;
            cp16(st + swz(r0c, c0c * 16), A + o0);
            cp16(st + swz(r1c, c1c * 16), A + o1);
        }
        {
            const int v0 = (n0 + r0c) < N, v1 = (n0 + r1c) < N;
            const size_t o0 = v0 ? (size_t)(n0 + r0c) * K + k0 + c0c * 8 : 0;
            const size_t o1 = v1 ? (size_t)(n0 + r1c) * K + k0 + c1c * 8 : 0;
            cp16z(st + TILE_B + swz(r0c, c0c * 16), B + o0, v0);
            cp16z(st + TILE_B + swz(r1c, c1c * 16), B + o1, v1);
        }
        CP_COMMIT();
    };

    load_stage(0, 0);
    load_stage(1, 1);
    load_stage(2, 2);

    const int a_row = lane & 15;
    const int a_kb  = (lane >> 4) << 4;
    const int b_row = (lane & 7) + ((lane >> 4) << 3);
    const int b_kb  = ((lane >> 3) & 1) << 4;

    for (int kc = 0; kc < nk; kc++) {
        CP_WAIT(2);
        __syncthreads();
        if (kc + 3 < nk) load_stage(kc + 3, (kc + 3) & 3);
        else CP_COMMIT();

        const uint32_t st = sb + (kc & 3) * STAGE_B;
        const uint32_t sA = st, sB = st + TILE_B;

#pragma unroll
        for (int kk = 0; kk < 2; kk++) {
            const int kb_a = kk * 32 + a_kb;
            const int kb_b = kk * 32 + b_kb;
            uint32_t ah[4][4], bh[2][4];
#pragma unroll
            for (int f = 0; f < 4; f++) {
                const int row = wm0 + f * 16 + a_row;
                ldsm_x4(ah[f][0], ah[f][1], ah[f][2], ah[f][3],
                        sA + swz(row, kb_a));
            }
#pragma unroll
            for (int g2 = 0; g2 < 2; g2++) {
                const int row = wn0 + g2 * 16 + b_row;
                ldsm_x4(bh[g2][0], bh[g2][1], bh[g2][2], bh[g2][3],
                        sB + swz(row, kb_b));
            }
#pragma unroll
            for (int f = 0; f < 4; f++)
#pragma unroll
                for (int g = 0; g < 4; g++) {
                    const uint32_t* bf = &bh[g >> 1][(g & 1) << 1];
                    mma_fp16(acc[f][g], ah[f], bf[0], bf[1]);
                }
        }
    }

    const int er = lane >> 2;
    const int ec = (lane & 3) << 1;
#pragma unroll
    for (int f = 0; f < 4; f++) {
        const int row = m0 + wm0 + f * 16 + er;
#pragma unroll
        for (int g = 0; g < 4; g++) {
            const int col = n0 + wn0 + g * 8 + ec;
            if (col < N) {
                store2(&C[(size_t)row * N + col], acc[f][g][0], acc[f][g][1]);
                store2(&C[(size_t)(row + 8) * N + col], acc[f][g][2],
                       acc[f][g][3]);
            }
        }
    }
}

// ------------------------- dt = softplus(raw + bias) ------------------------
__global__ void dt_kernel(const float* __restrict__ dt_bias) {
    const int idx = blockIdx.x * 256 + threadIdx.x;
    const int m = idx >> 5;
    const int h = idx & 31;
    float v = __half2float(
                  g_zxbcdt[(size_t)m * D_IN_PROJ + (D_INNER + CONV_DIM) + h]) +
              dt_bias[h];
    g_dt[idx] = (v > 20.f) ? v : log1pf(expf(v));
}

// ------------------------- tiled depthwise conv + SiLU -> fp16 --------------
__global__ void __launch_bounds__(256) conv_silu_kernel(
    const float* __restrict__ w, const float* __restrict__ bias) {
    __shared__ float sx[67][128];
    const int cb = blockIdx.x;
    const int tb = blockIdx.y;
    const int tid = threadIdx.x;
    const int m0 = tb * 64;
    const int zero_head = ((m0 & (T_LEN - 1)) == 0);

    for (int idx = tid; idx < 67 * 128; idx += 256) {
        const int r = idx >> 7, ch = idx & 127;
        float v = 0.f;
        if (r >= 3 || !zero_head)
            v = __half2float(g_zxbcdt[(size_t)(m0 - 3 + r) * D_IN_PROJ +
                                      D_INNER + cb * 128 + ch]);
        sx[r][ch] = v;
    }
    __syncthreads();

    const int ch = tid & 127;
    const int th = (tid >> 7) * 32;
    const int gc = cb * 128 + ch;
    const float w0 = w[gc * 4 + 0], w1 = w[gc * 4 + 1];
    const float w2 = w[gc * 4 + 2], w3 = w[gc * 4 + 3];
    const float bz = bias[gc];
#pragma unroll 8
    for (int i = 0; i < 32; i++) {
        const int t = th + i;
        float acc = bz + w0 * sx[t][ch] + w1 * sx[t + 1][ch] +
                    w2 * sx[t + 2][ch] + w3 * sx[t + 3][ch];
        g_xbc[(size_t)(m0 + t) * CONV_DIM + gc] =
            __float2half_rn(acc / (1.f + expf(-acc)));
    }
}

// ------------------------- SSD phase 1 (fp16 tensor cores) ------------------
#define OFF_X 0
#define OFF_B 8192
#define OFF_C 16384
#define OFF_M 24576
__global__ void __launch_bounds__(256) ssd1_tc(const float* __restrict__ A_log,
                                               const float* __restrict__ Dvec) {
    __shared__ __align__(16) char sm[32768];
    __shared__ float s_cum[64], s_dt[64], s_coef[64];
    const uint32_t sb = smem_u32(sm);

    const int blk = blockIdx.x;
    const int c   = blk & (NCHUNK - 1);
    const int bh  = blk >> 6;
    const int b = bh >> 5, h = bh & 31;
    const int tid = threadIdx.x, wid = tid >> 5, lane = tid & 31;
    const int r0 = (wid & 3) * 16, c0 = (wid >> 2) * 32;
    const int m0 = b * T_LEN + c * CHUNK;
    const float Ahc = -expf(A_log[h]);
    const float Dh  = Dvec[h];

#pragma unroll
    for (int i = 0; i < 6; i++) {
        int flat = tid + (i << 8);
        int t3 = flat >> 9;
        int wt = flat & 511;
        int l = wt >> 3, j = wt & 7;
        int off = (t3 == 0) ? h * HEADDIM : (t3 == 1) ? D_INNER
                                                      : D_INNER + D_STATE;
        cp16(sb + t3 * 8192 + swz128(l, j * 16),
             g_xbc + (size_t)(m0 + l) * CONV_DIM + off + j * 8);
    }
    CP_COMMIT();
    if (tid < 64) s_dt[tid] = g_dt[(size_t)(m0 + tid) * NHEADS + h];
    CP_WAIT(0);
    __syncthreads();
    if (wid == 0) {
        float v0 = Ahc * s_dt[lane * 2], v1 = Ahc * s_dt[lane * 2 + 1];
        float s = v0 + v1;
#pragma unroll
        for (int o = 1; o < 32; o <<= 1) {
            float t = __shfl_up_sync(0xFFFFFFFF, s, o);
            if (lane >= o) s += t;
        }
        float excl = s - (v0 + v1);
        s_cum[lane * 2] = excl + v0;
        s_cum[lane * 2 + 1] = excl + v0 + v1;
    }
    __syncthreads();
    if (tid < 64) {
        s_coef[tid] = s_dt[tid] * __expf(s_cum[63] - s_cum[tid]);
        g_el[(size_t)blk * 64 + tid] = __expf(s_cum[tid]);
    }
    if (tid == 0) g_T[blk] = __expf(s_cum[63]);
    __syncthreads();

    const int er = lane >> 2, ec = (lane & 3) << 1;

    // ---- step A: G = C @ B^T, mask/decay -> M (fp16) ----
    {
        float acc[4][4];
#pragma unroll
        for (int g = 0; g < 4; g++)
#pragma unroll
            for (int e = 0; e < 4; e++) acc[g][e] = 0.f;
#pragma unroll
        for (int k16 = 0; k16 < 4; k16++) {
            uint32_t ah[4];
            uint32_t aoff = swz128(r0 + (lane & 15),
                                   k16 * 32 + ((lane >> 4) << 4));
            ldsm_x4(ah[0], ah[1], ah[2], ah[3], sb + OFF_C + aoff);
            uint32_t bhf[2][4];
#pragma unroll
            for (int g2 = 0; g2 < 2; g2++) {
                uint32_t boff =
                    swz128(c0 + g2 * 16 + (lane & 7) + ((lane >> 4) << 3),
                           k16 * 32 + (((lane >> 3) & 1) << 4));
                ldsm_x4(bhf[g2][0], bhf[g2][1], bhf[g2][2], bhf[g2][3],
                        sb + OFF_B + boff);
            }
#pragma unroll
            for (int g = 0; g < 4; g++) {
                const uint32_t* bf = &bhf[g >> 1][(g & 1) << 1];
                mma_fp16(acc[g], ah, bf[0], bf[1]);
            }
        }
#pragma unroll
        for (int g = 0; g < 4; g++) {
            int s0 = c0 + g * 8 + ec;
            float cs0 = s_cum[s0], cs1 = s_cum[s0 + 1];
            float d0 = s_dt[s0], d1 = s_dt[s0 + 1];
#pragma unroll
            for (int hf = 0; hf < 2; hf++) {
                int l = r0 + er + hf * 8;
                float cl = s_cum[l];
                float v0 = (s0     <= l) ? acc[g][hf * 2 + 0] * __expf(cl - cs0) * d0 : 0.f;
                float v1 = (s0 + 1 <= l) ? acc[g][hf * 2 + 1] * __expf(cl - cs1) * d1 : 0.f;
                *(uint32_t*)(sm + OFF_M + swz128(l, s0 * 2)) = packh2(v0, v1);
            }
        }
    }
    __syncthreads();

    // ---- CX = coef(l) * x (overwrites C tile) ----
#pragma unroll
    for (int i = 0; i < 8; i++) {
        int flat = tid + (i << 8);
        int l = flat >> 5, q2 = flat & 31;
        uint32_t so = swz128(l, q2 * 4);
        float2 v = unpackh2(*(uint32_t*)(sm + OFF_X + so));
        float cf = s_coef[l];
        *(uint32_t*)(sm + OFF_C + so) = packh2(v.x * cf, v.y * cf);
    }

    // ---- step B: Y = M @ x (+ D skip) -> fp16 g_y ----
    {
        float acc[4][4];
#pragma unroll
        for (int g = 0; g < 4; g++)
#pragma unroll
            for (int e = 0; e < 4; e++) acc[g][e] = 0.f;
#pragma unroll
        for (int k16 = 0; k16 < 4; k16++) {
            uint32_t ah[4];
            uint32_t aoff = swz128(r0 + (lane & 15),
                                   k16 * 32 + ((lane >> 4) << 4));
            ldsm_x4(ah[0], ah[1], ah[2], ah[3], sb + OFF_M + aoff);
            uint32_t bhf[2][4];
#pragma unroll
            for (int g2 = 0; g2 < 2; g2++) {
                uint32_t boff =
                    swz128(k16 * 16 + ((lane >> 3) & 1) * 8 + (lane & 7),
                           (c0 + g2 * 16) * 2 + (((lane >> 4) & 1) << 4));
                ldsm_x4_t(bhf[g2][0], bhf[g2][1], bhf[g2][2], bhf[g2][3],
                          sb + OFF_X + boff);
            }
#pragma unroll
            for (int g = 0; g < 4; g++) {
                const uint32_t* bf = &bhf[g >> 1][(g & 1) << 1];
                mma_fp16(acc[g], ah, bf[0], bf[1]);
            }
        }
#pragma unroll
        for (int g = 0; g < 4; g++) {
            int p0 = c0 + g * 8 + ec;
#pragma unroll
            for (int hf = 0; hf < 2; hf++) {
                int l = r0 + er + hf * 8;
                float2 xv = unpackh2(*(uint32_t*)(sm + OFF_X + swz128(l, p0 * 2)));
                *(uint32_t*)&g_y[(size_t)(m0 + l) * D_INNER + h * HEADDIM + p0] =
                    packh2(acc[g][hf * 2 + 0] + Dh * xv.x,
                           acc[g][hf * 2 + 1] + Dh * xv.y);
            }
        }
    }
    __syncthreads();

    // ---- step C: S(p,n) = CX^T @ B -> fp16 g_cs ----
    {
        float acc[4][4];
#pragma unroll
        for (int g = 0; g < 4; g++)
#pragma unroll
            for (int e = 0; e < 4; e++) acc[g][e] = 0.f;
#pragma unroll
        for (int k16 = 0; k16 < 4; k16++) {
            uint32_t ah[4];
            uint32_t aoff =
                swz128(k16 * 16 + ((lane >> 4) & 1) * 8 + (lane & 7),
                       r0 * 2 + (((lane >> 3) & 1) << 4));
            ldsm_x4_t(ah[0], ah[1], ah[2], ah[3], sb + OFF_C + aoff);
            uint32_t bhf[2][4];
#pragma unroll
            for (int g2 = 0; g2 < 2; g2++) {
                uint32_t boff =
                    swz128(k16 * 16 + ((lane >> 3) & 1) * 8 + (lane & 7),
                           (c0 + g2 * 16) * 2 + (((lane >> 4) & 1) << 4));
                ldsm_x4_t(bhf[g2][0], bhf[g2][1], bhf[g2][2], bhf[g2][3],
                          sb + OFF_B + boff);
            }
#pragma unroll
            for (int g = 0; g < 4; g++) {
                const uint32_t* bf = &bhf[g >> 1][(g & 1) << 1];
                mma_fp16(acc[g], ah, bf[0], bf[1]);
            }
        }
        const size_t sbase = (size_t)blk * 4096;
#pragma unroll
        for (int g = 0; g < 4; g++) {
            int n0 = c0 + g * 8 + ec;
#pragma unroll
            for (int hf = 0; hf < 2; hf++) {
                int p = r0 + er + hf * 8;
                *(uint32_t*)&g_cs[sbase + p * 64 + n0] =
                    packh2(acc[g][hf * 2 + 0], acc[g][hf * 2 + 1]);
            }
        }
    }
}

// ------------------------- SSD phase 2: inter-chunk scan (8x parallel) ------
__global__ void __launch_bounds__(256) ssd_phase2() {
    const int slice = blockIdx.x & 7;
    const int bh    = blockIdx.x >> 3;
    const int off   = slice * 512 + threadIdx.x * 2;
    float s0 = 0.f, s1 = 0.f;
    const size_t b0 = (size_t)bh * NCHUNK * 4096;
    const float* Tp = &g_T[bh * NCHUNK];
#pragma unroll 4
    for (int c = 0; c < NCHUNK; c++) {
        const size_t base = b0 + (size_t)c * 4096 + off;
        *(uint32_t*)&g_ps[base] = packh2(s0, s1);
        float2 v = unpackh2(*(const uint32_t*)&g_cs[base]);
        const float T = Tp[c];
        s0 = s0 * T + v.x;
        s1 = s1 * T + v.y;
    }
}

// ------------------------- SSD phase 3 (fp16 tensor cores) ------------------
__global__ void __launch_bounds__(256) ssd3_tc() {
    __shared__ __align__(16) char t_C[8192];
    __shared__ __align__(16) char t_S[8192];
    __shared__ float s_el[64];
    const uint32_t aC = smem_u32(t_C), aS = smem_u32(t_S);

    const int blk = blockIdx.x;
    const int c   = blk & (NCHUNK - 1);
    const int bh  = blk >> 6;
    const int b = bh >> 5, h = bh & 31;
    const int tid = threadIdx.x, wid = tid >> 5, lane = tid & 31;
    const int r0 = (wid & 3) * 16, c0 = (wid >> 2) * 32;
    const int m0 = b * T_LEN + c * CHUNK;

    // C tile + S tile via cp.async (512 chunks each)
#pragma unroll
    for (int i = 0; i < 2; i++) {
        int flat = tid + (i << 8);
        int l = flat >> 3, j = flat & 7;
        cp16(aC + swz128(l, j * 16),
             g_xbc + (size_t)(m0 + l) * CONV_DIM + D_INNER + D_STATE + j * 8);
        cp16(aS + swz128(l, j * 16),
             g_ps + (size_t)blk * 4096 + l * 64 + j * 8);
    }
    CP_COMMIT();
    if (tid < 64) s_el[tid] = g_el[(size_t)blk * 64 + tid];
    CP_WAIT(0);
    __syncthreads();

    float acc[4][4];
#pragma unroll
    for (int g = 0; g < 4; g++)
#pragma unroll
        for (int e = 0; e < 4; e++) acc[g][e] = 0.f;
#pragma unroll
    for (int k16 = 0; k16 < 4; k16++) {
        uint32_t ah[4];
        uint32_t aoff = swz128(r0 + (lane & 15), k16 * 32 + ((lane >> 4) << 4));
        ldsm_x4(ah[0], ah[1], ah[2], ah[3], aC + aoff);
        uint32_t bhf[2][4];
#pragma unroll
        for (int g2 = 0; g2 < 2; g2++) {
            uint32_t boff =
                swz128(c0 + g2 * 16 + (lane & 7) + ((lane >> 4) << 3),
                       k16 * 32 + (((lane >> 3) & 1) << 4));
            ldsm_x4(bhf[g2][0], bhf[g2][1], bhf[g2][2], bhf[g2][3], aS + boff);
        }
#pragma unroll
        for (int g = 0; g < 4; g++) {
            const uint32_t* bf = &bhf[g >> 1][(g & 1) << 1];
            mma_fp16(acc[g], ah, bf[0], bf[1]);
        }
    }
    const int er = lane >> 2, ec = (lane & 3) << 1;
#pragma unroll
    for (int g = 0; g < 4; g++) {
        int p0 = c0 + g * 8 + ec;
#pragma unroll
        for (int hf = 0; hf < 2; hf++) {
            int l = r0 + er + hf * 8;
            float el = s_el[l];
            uint32_t* yp =
                (uint32_t*)&g_y[(size_t)(m0 + l) * D_INNER + h * HEADDIM + p0];
            float2 cur = unpackh2(*yp);
            *yp = packh2(cur.x + el * acc[g][hf * 2 + 0],
                         cur.y + el * acc[g][hf * 2 + 1]);
        }
    }
}

// ------------------------- gate + RMSNorm -> fp16 ---------------------------
__global__ void gate_rms_kernel(const float* __restrict__ norm_w,
                                __half* __restrict__ yh) {
    const int m = blockIdx.x;
    const int tid = threadIdx.x;
    const size_t ybase = (size_t)m * D_INNER;
    const size_t zbase = (size_t)m * D_IN_PROJ;
    float vals[8];
    float ssum = 0.f;
#pragma unroll
    for (int i = 0; i < 8; i++) {
        const int idx = tid + i * 256;
        const float yv = __half2float(g_y[ybase + idx]);
        const float z = __half2float(g_zxbcdt[zbase + idx]);
        const float g = yv * z / (1.f + expf(-z));
        vals[i] = g;
        ssum += g * g;
    }
    __shared__ float red[256];
    red[tid] = ssum;
    __syncthreads();
    for (int s = 128; s > 0; s >>= 1) {
        if (tid < s) red[tid] += red[tid + s];
        __syncthreads();
    }
    const float scale = rsqrtf(red[0] / (float)D_INNER + 1e-5f);
#pragma unroll
    for (int i = 0; i < 8; i++) {
        const int idx = tid + i * 256;
        yh[ybase + idx] = __float2half_rn(vals[i] * scale * norm_w[idx]);
    }
}

// ---------------------------------------------------------------------------
extern "C" void kernel_launch(void* const* d_in, const int* in_sizes, int n_in,
                              void* d_out, int out_size) {
    const float* u       = (const float*)d_in[0];
    const float* W_in    = (const float*)d_in[1];
    const float* conv_w  = (const float*)d_in[2];
    const float* conv_b  = (const float*)d_in[3];
    const float* dt_bias = (const float*)d_in[4];
    const float* A_log   = (const float*)d_in[5];
    const float* Dv      = (const float*)d_in[6];
    const float* norm_w  = (const float*)d_in[7];
    const float* W_out   = (const float*)d_in[8];
    float* out = (float*)d_out;

    __half *zx_p, *uh, *wih, *yh, *woh;
    cudaGetSymbolAddress((void**)&zx_p, g_zxbcdt);
    cudaGetSymbolAddress((void**)&uh, g_uh);
    cudaGetSymbolAddress((void**)&wih, g_wih);
    cudaGetSymbolAddress((void**)&yh, g_yh);
    cudaGetSymbolAddress((void**)&woh, g_woh);

    cudaFuncSetAttribute(gemm_mma_kernel<__half>,
                         cudaFuncAttributeMaxDynamicSharedMemorySize, GEMM_SMEM);
    cudaFuncSetAttribute(gemm_mma_kernel<float>,
                         cudaFuncAttributeMaxDynamicSharedMemorySize, GEMM_SMEM);

    {
        int n = M_TOK * D_MODEL;
        cvt_kernel<<<(n / 2 + 255) / 256, 256>>>(u, uh, n);
        n = D_IN_PROJ * D_MODEL;
        cvt_kernel<<<(n / 2 + 255) / 256, 256>>>(W_in, wih, n);
    }

    gemm_mma_kernel<__half>
        <<<dim3((D_IN_PROJ + 127) / 128, M_TOK / 128), 256, GEMM_SMEM>>>(
            uh, wih, zx_p, M_TOK, D_IN_PROJ, D_MODEL);

    dt_kernel<<<(M_TOK * NHEADS) / 256, 256>>>(dt_bias);
    conv_silu_kernel<<<dim3(CONV_DIM / 128, M_TOK / 64), 256>>>(conv_w, conv_b);

    ssd1_tc<<<NBH * NCHUNK, 256>>>(A_log, Dv);
    ssd_phase2<<<NBH * 8, 256>>>();
    ssd3_tc<<<NBH * NCHUNK, 256>>>();

    gate_rms_kernel<<<M_TOK, 256>>>(norm_w, yh);

    {
        int n = D_MODEL * D_INNER;
        cvt_kernel<<<(n / 2 + 255) / 256, 256>>>(W_out, woh, n);
    }

    gemm_mma_kernel<float>
        <<<dim3(D_MODEL / 128, M_TOK / 128), 256, GEMM_SMEM>>>(
            yh, woh, out, M_TOK, D_MODEL, D_INNER);
}